// round 4
// baseline (speedup 1.0000x reference)
#include <cuda_runtime.h>
#include <cstdint>

#define BATCH 32
#define NODES 1365         // nodes levels 0..5
#define NODES_ALL 5461     // nodes levels 0..6

static const long long TOK_ELEMS = (long long)BATCH * NODES_ALL * 192; // 33,552,384
static const long long MASK_OFF_ = TOK_ELEMS;
static const long long INFO_OFF_ = TOK_ELEMS + (long long)BATCH * NODES_ALL;

__device__ __constant__ int c_off[8] = {0, 1, 5, 21, 85, 341, 1365, 5461};

// ---- scratch (device globals; no allocations allowed) ----
__device__ float g_sum[BATCH * NODES];
__device__ float g_ssq[BATCH * NODES];
__device__ float g_edge[BATCH * NODES];
__device__ float g_epart[BATCH * 4 * 256];           // per-tile partial edge sums, levels 0..3
__device__ unsigned char g_split[BATCH * NODES];
__device__ int g_cnt[BATCH];                          // zero-init; self-resetting tickets

// ============================================================
// K1: fused gray + level-5 stats + per-level Sobel edge sums
//     + (last CTA per batch) full tree aggregation.
// One CTA = one 32x32 pixel tile (1024 threads); gray never hits HBM.
// ============================================================
__global__ void k_gray_edge(const float* __restrict__ img) {
    int b = blockIdx.y;
    int ty = blockIdx.x >> 4, tx = blockIdx.x & 15;
    __shared__ float sg[34][36];
    __shared__ float sred[5][32];
    __shared__ float s5[64];
    __shared__ float sh_s[64], sh_q[64];   // stats: [row][half]
    __shared__ int sticket;
    int t = threadIdx.x;
    int py = t >> 5, px = t & 31;
    int Y = ty * 32 + py, X = tx * 32 + px;

    const float* ib = img + (size_t)b * 3 * 262144;
    size_t pidx = (size_t)Y * 512 + X;
    float c0 = ib[pidx];
    float c1 = ib[pidx + 262144];
    float c2 = ib[pidx + 524288];
    float s  = c0 + c1 + c2;
    float ss = c0 * c0 + c1 * c1 + c2 * c2;
    sg[py + 1][px + 1] = s * (1.0f / 3.0f);

    // halo: 132 perimeter pixels of the 34x34 window
    if (t < 132) {
        int sy, sx;
        if (t < 34)       { sy = 0;           sx = t; }
        else if (t < 68)  { sy = 33;          sx = t - 34; }
        else if (t < 100) { sy = t - 68 + 1;  sx = 0; }
        else              { sy = t - 100 + 1; sx = 33; }
        int gy = ty * 32 - 1 + sy, gx = tx * 32 - 1 + sx;
        float v = 0.0f;
        if (gy >= 0 && gy < 512 && gx >= 0 && gx < 512) {
            size_t q = (size_t)gy * 512 + gx;
            v = (ib[q] + ib[q + 262144] + ib[q + 524288]) * (1.0f / 3.0f);
        }
        sg[sy][sx] = v;
    }
    __syncthreads();

    // Sobel neighborhood (sg origin is at (-1,-1) of the tile)
    float gNW = sg[py][px],     gN = sg[py][px + 1],     gNE = sg[py][px + 2];
    float gW  = sg[py + 1][px],                          gE  = sg[py + 1][px + 2];
    float gSW = sg[py + 2][px], gS = sg[py + 2][px + 1], gSE = sg[py + 2][px + 2];

    float mag[6];
    #pragma unroll
    for (int l = 0; l < 6; l++) {
        int hm = (512 >> l) - 1;
        float vt = (Y & hm) ? 1.0f : 0.0f;
        float vb = ((Y & hm) != hm) ? 1.0f : 0.0f;
        float vl = (X & hm) ? 1.0f : 0.0f;
        float vr = ((X & hm) != hm) ? 1.0f : 0.0f;
        float ex = vr * (vt * gNE + 2.0f * gE + vb * gSE)
                 - vl * (vt * gNW + 2.0f * gW + vb * gSW);
        float ey = vb * (vl * gSW + 2.0f * gS + vr * gSE)
                 - vt * (vl * gNW + 2.0f * gN + vr * gNE);
        mag[l] = sqrtf(ex * ex + ey * ey);
    }

    // --- stats: half-warp reduce (16x16 quadrant rows)
    #pragma unroll
    for (int o = 8; o; o >>= 1) {
        s  += __shfl_xor_sync(0xffffffffu, s,  o);
        ss += __shfl_xor_sync(0xffffffffu, ss, o);
    }
    if ((px & 15) == 0) {
        int h = px >> 4;
        sh_s[(py << 1) | h] = s;
        sh_q[(py << 1) | h] = ss;
    }
    // --- levels 0..4: full-warp row sums (no syncs between)
    #pragma unroll
    for (int l = 0; l < 5; l++) {
        float v = mag[l];
        #pragma unroll
        for (int o = 16; o; o >>= 1) v += __shfl_xor_sync(0xffffffffu, v, o);
        if (px == 0) sred[l][py] = v;
    }
    // --- level 5: half-warp row sums
    {
        float v = mag[5];
        #pragma unroll
        for (int o = 8; o; o >>= 1) v += __shfl_xor_sync(0xffffffffu, v, o);
        if ((px & 15) == 0) s5[py * 2 + (px >> 4)] = v;
    }
    __syncthreads();

    float* eb = g_edge + (size_t)b * NODES;
    if (t < 160) {                     // warps 0..4 finish levels 0..4
        int l = t >> 5, lane = t & 31;
        float w = sred[l][lane];
        #pragma unroll
        for (int o = 16; o; o >>= 1) w += __shfl_xor_sync(0xffffffffu, w, o);
        if (lane == 0) {
            if (l == 4) eb[85 + ty * 16 + tx] = w;
            else        g_epart[(b * 4 + l) * 256 + ty * 16 + tx] = w;
        }
    }
    if (t >= 256 && t < 260) {         // stats quadrants
        int q = t - 256, qy = q >> 1, qx = q & 1;
        float as = 0.0f, aq = 0.0f;
        #pragma unroll
        for (int r = 0; r < 16; r++) {
            as += sh_s[(qy * 16 + r) * 2 + qx];
            aq += sh_q[(qy * 16 + r) * 2 + qx];
        }
        int leaf = (ty * 2 + qy) * 32 + (tx * 2 + qx);
        g_sum[b * NODES + 341 + leaf] = as;
        g_ssq[b * NODES + 341 + leaf] = aq;
    }
    if (t >= 288 && t < 292) {         // level-5 edge quadrants
        int q = t - 288, qy = q >> 1, qx = q & 1;
        float w = 0.0f;
        #pragma unroll
        for (int r = 0; r < 16; r++) w += s5[(qy * 16 + r) * 2 + qx];
        eb[341 + (ty * 2 + qy) * 32 + (tx * 2 + qx)] = w;
    }

    // ---- last-CTA-per-batch aggregation (threadfence reduction pattern)
    __threadfence();
    __syncthreads();
    if (t == 0) sticket = atomicAdd(&g_cnt[b], 1);
    __syncthreads();
    if (sticket == 255) {
        __threadfence();
        // edge levels 0..3 from per-tile partials
        if (t < 85) {
            int l = t < 1 ? 0 : t < 5 ? 1 : t < 21 ? 2 : 3;
            int idx = t - c_off[l];
            int n = 1 << l, P = 16 >> l;
            int r = idx >> l, c = idx & (n - 1);
            float acc = 0.0f;
            const float* ep = g_epart + (b * 4 + l) * 256;
            for (int dy = 0; dy < P; dy++)
                for (int dx = 0; dx < P; dx++)
                    acc += ep[(r * P + dy) * 16 + (c * P + dx)];
            eb[t] = acc;
        }
        // sum/ssq quadtree aggregation, levels 4..0
        float* S = g_sum + (size_t)b * NODES;
        float* Q = g_ssq + (size_t)b * NODES;
        for (int l = 4; l >= 0; l--) {
            int n = 1 << l, nn = n << 1;
            int cb = c_off[l + 1], ob = c_off[l];
            for (int i = t; i < n * n; i += blockDim.x) {
                int r = i >> l, c = i & (n - 1);
                int k0 = cb + (2 * r) * nn + 2 * c;
                int k2 = k0 + nn;
                S[ob + i] = S[k0] + S[k0 + 1] + S[k2] + S[k2 + 1];
                Q[ob + i] = Q[k0] + Q[k0 + 1] + Q[k2] + Q[k2 + 1];
            }
            __syncthreads();
        }
        if (t == 0) g_cnt[b] = 0;   // reset for next graph replay
    }
}

// ============================================================
// K2: tiled MLP. 64 items per CTA (107KB smem -> 2 CTAs/SM).
// split = (logit >= 0)  (sigmoid(x)>=0.5 <=> x>=0)
// ============================================================
#define MLP_ITEMS 64
#define MLP_SMEM_FLOATS 26752   // 107,008 bytes

__global__ void k_mlp(const float* __restrict__ W1, const float* __restrict__ b1,
                      const float* __restrict__ W2, const float* __restrict__ b2,
                      const float* __restrict__ W3, const float* __restrict__ b3,
                      const float* __restrict__ W4, const float* __restrict__ b4) {
    extern __shared__ float sm[];
    float* sW1 = sm;                 // 768
    float* sb1 = sW1 + 768;          // 128
    float* sW2 = sb1 + 128;          // 8192
    float* sb2 = sW2 + 8192;         // 64
    float* sW3 = sb2 + 64;           // 2048
    float* sb3 = sW3 + 2048;         // 32
    float* sW4 = sb3 + 32;           // 32
    float* sF  = sW4 + 32;           // 6*64
    float* sH1 = sF + 384;           // 64*132
    float* sH2 = sH1 + 64 * 132;     // 64*68
    float* sH3 = sH2 + 64 * 68;      // 64*36

    int t = threadIdx.x;  // 256
    for (int i = t; i < 768; i += 256) sW1[i] = W1[i];
    for (int i = t; i < 128; i += 256) sb1[i] = b1[i];
    for (int i = t; i < 8192; i += 256) sW2[i] = W2[i];
    if (t < 64) sb2[t] = b2[t];
    for (int i = t; i < 2048; i += 256) sW3[i] = W3[i];
    if (t < 32) { sb3[t] = b3[t]; sW4[t] = W4[t]; }
    float bias4 = b4[0];
    int base = blockIdx.x * MLP_ITEMS;

    // phase 1: features
    if (t < MLP_ITEMS) {
        int item = base + t;
        float f0 = 0, f1 = 0, fv = 0, fm = 0, fe = 0;
        if (item < BATCH * NODES) {
            int node = item % NODES;
            int l = node < 1 ? 0 : node < 5 ? 1 : node < 21 ? 2 : node < 85 ? 3 : node < 341 ? 4 : 5;
            int hl = 512 >> l;
            float N = 3.0f * (float)hl * (float)hl;
            float s = g_sum[item], q = g_ssq[item], e = g_edge[item];
            float mean = s / N;
            float var = (q - s * mean) / (N - 1.0f);
            float edge = e / ((float)hl * (float)hl);
            f0 = (float)l; f1 = (float)hl; fv = var; fm = mean; fe = edge;
        }
        sF[0 * 64 + t] = f0;
        sF[1 * 64 + t] = f1;
        sF[2 * 64 + t] = f1;
        sF[3 * 64 + t] = fv;
        sF[4 * 64 + t] = fm;
        sF[5 * 64 + t] = fe;
    }
    __syncthreads();

    // phase 2: H1 = relu(F @ W1 + b1)   thread: 1 item, 32 outputs
    {
        int it = t >> 2;
        int j0 = (t & 3) * 32;
        float f[6];
        #pragma unroll
        for (int i = 0; i < 6; i++) f[i] = sF[i * 64 + it];
        for (int j = j0; j < j0 + 32; j++) {
            float acc = sb1[j];
            #pragma unroll
            for (int i = 0; i < 6; i++) acc += f[i] * sW1[i * 128 + j];
            sH1[it * 132 + j] = fmaxf(acc, 0.0f);
        }
    }
    __syncthreads();

    // phase 3: H2 = relu(H1 @ W2 + b2)   thread: 2 items x 8 outputs
    {
        int it0 = (t >> 3) * 2;
        int j0 = (t & 7) * 8;
        float acc[2][8];
        #pragma unroll
        for (int m = 0; m < 2; m++)
            #pragma unroll
            for (int j = 0; j < 8; j++) acc[m][j] = sb2[j0 + j];
        for (int i = 0; i < 128; i += 4) {
            float a[2][4];
            #pragma unroll
            for (int m = 0; m < 2; m++) {
                float4 v = *(const float4*)&sH1[(it0 + m) * 132 + i];
                a[m][0] = v.x; a[m][1] = v.y; a[m][2] = v.z; a[m][3] = v.w;
            }
            #pragma unroll
            for (int k = 0; k < 4; k++) {
                float4 w0 = *(const float4*)&sW2[(i + k) * 64 + j0];
                float4 w1 = *(const float4*)&sW2[(i + k) * 64 + j0 + 4];
                float wv[8] = {w0.x, w0.y, w0.z, w0.w, w1.x, w1.y, w1.z, w1.w};
                #pragma unroll
                for (int m = 0; m < 2; m++)
                    #pragma unroll
                    for (int j = 0; j < 8; j++) acc[m][j] += a[m][k] * wv[j];
            }
        }
        #pragma unroll
        for (int m = 0; m < 2; m++)
            #pragma unroll
            for (int j = 0; j < 8; j++)
                sH2[(it0 + m) * 68 + j0 + j] = fmaxf(acc[m][j], 0.0f);
    }
    __syncthreads();

    // phase 4: H3 = relu(H2 @ W3 + b3)   thread: 1 item x 8 outputs
    {
        int it = t >> 2;
        int j0 = (t & 3) * 8;
        float acc[8];
        #pragma unroll
        for (int j = 0; j < 8; j++) acc[j] = sb3[j0 + j];
        for (int i = 0; i < 64; i += 4) {
            float4 v = *(const float4*)&sH2[it * 68 + i];
            float a[4] = {v.x, v.y, v.z, v.w};
            #pragma unroll
            for (int k = 0; k < 4; k++) {
                float4 w0 = *(const float4*)&sW3[(i + k) * 32 + j0];
                float4 w1 = *(const float4*)&sW3[(i + k) * 32 + j0 + 4];
                float wv[8] = {w0.x, w0.y, w0.z, w0.w, w1.x, w1.y, w1.z, w1.w};
                #pragma unroll
                for (int j = 0; j < 8; j++) acc[j] += a[k] * wv[j];
            }
        }
        #pragma unroll
        for (int j = 0; j < 8; j++)
            sH3[it * 36 + j0 + j] = fmaxf(acc[j], 0.0f);
    }
    __syncthreads();

    // phase 5: logit sign
    if (t < MLP_ITEMS) {
        int item = base + t;
        float acc = bias4;
        #pragma unroll
        for (int k = 0; k < 32; k += 4) {
            float4 h = *(const float4*)&sH3[t * 36 + k];
            float4 w = *(const float4*)&sW4[k];
            acc += h.x * w.x + h.y * w.y + h.z * w.z + h.w * w.w;
        }
        if (item < BATCH * NODES) g_split[item] = (unsigned char)(acc >= 0.0f);
    }
}

// ============================================================
// K3: write tokens (Hilbert-DFS order), mask, level_info.
// Mask computed inline from <=6 ancestor split flags (uniform loads).
// Masked-out tokens are exact zeros -> skip the image read entirely.
// ============================================================
__global__ void k_write(const float* __restrict__ img, float* __restrict__ out) {
    int gw = blockIdx.x * 8 + (threadIdx.x >> 5);
    if (gw >= BATCH * NODES_ALL) return;
    int lane = threadIdx.x & 31;
    int b = gw / NODES_ALL;
    int p = gw - b * NODES_ALL;

    // decode DFS position -> (level,row,col,path)
    int level = 0, row = 0, col = 0, pp = p, plen = 0;
    unsigned pathbits = 0;
    while (pp > 0) {
        pp--;
        int s = ((1 << (2 * (6 - level))) - 1) / 3;   // child subtree size
        int ci = pp / s;
        pp -= ci * s;
        int q = (0x3102 >> (ci * 4)) & 0xF;           // HILBERT = [2,0,1,3]
        row = 2 * row + (q >> 1);
        col = 2 * col + (q & 1);
        pathbits |= (unsigned)q << (3 * plen);
        plen++;
        level++;
    }

    // mask from ancestor split chain
    const unsigned char* sp = g_split + (size_t)b * NODES;
    bool alive = true;
    for (int j = 0; j < level; j++) {
        int idx = c_off[j] + ((row >> (level - j)) << j) + (col >> (level - j));
        alive = alive && (sp[idx] != 0);
    }
    float m;
    if (level < 6) m = (alive && sp[c_off[level] + (row << level) + col] == 0) ? 1.0f : 0.0f;
    else           m = alive ? 1.0f : 0.0f;

    float* o = out + (size_t)gw * 192;
    if (m != 0.0f) {
        int hl = 512 >> level;
        int Y0 = row * hl + ((hl - 8) >> 1);
        int X0 = col * hl + ((hl - 8) >> 1);
        if (lane < 24) {
            int c = lane >> 3, r = lane & 7;
            const float* src = img + ((size_t)(b * 3 + c) * 512 + (size_t)(Y0 + r)) * 512 + X0;
            float4 v0 = __ldg((const float4*)src);
            float4 v1 = __ldg((const float4*)(src + 4));
            float* dst = o + c * 64 + r * 8;
            *(float4*)dst = v0;
            *(float4*)(dst + 4) = v1;
        }
    } else {
        float4 z = make_float4(0.0f, 0.0f, 0.0f, 0.0f);
        if (lane < 24) {
            float* dst = o + lane * 8;
            *(float4*)dst = z;
            *(float4*)(dst + 4) = z;
        }
    }
    if (lane == 24) out[MASK_OFF_ + (size_t)gw] = m;
    if (b == 0 && lane >= 25 && lane < 27) {
        int base16 = (lane - 25) * 8;
        #pragma unroll
        for (int k = 0; k < 8; k++) {
            int slot = base16 + k;
            float v = 0.0f;
            if (slot == 0) v = (float)level;
            else if (slot - 1 < plen) v = (float)((pathbits >> (3 * (slot - 1))) & 7);
            out[INFO_OFF_ + (size_t)p * 16 + slot] = v;
        }
    }
}

// ============================================================
extern "C" void kernel_launch(void* const* d_in, const int* in_sizes, int n_in,
                              void* d_out, int out_size) {
    const float* img = (const float*)d_in[0];
    const float* W1 = (const float*)d_in[1];
    const float* b1 = (const float*)d_in[2];
    const float* W2 = (const float*)d_in[3];
    const float* b2 = (const float*)d_in[4];
    const float* W3 = (const float*)d_in[5];
    const float* b3 = (const float*)d_in[6];
    const float* W4 = (const float*)d_in[7];
    const float* b4 = (const float*)d_in[8];
    float* out = (float*)d_out;

    cudaFuncSetAttribute(k_mlp, cudaFuncAttributeMaxDynamicSharedMemorySize,
                         MLP_SMEM_FLOATS * (int)sizeof(float));

    k_gray_edge<<<dim3(256, BATCH), 1024>>>(img);
    int mlp_blocks = (BATCH * NODES + MLP_ITEMS - 1) / MLP_ITEMS;  // 683
    k_mlp<<<mlp_blocks, 256, MLP_SMEM_FLOATS * sizeof(float)>>>(W1, b1, W2, b2, W3, b3, W4, b4);
    k_write<<<(BATCH * NODES_ALL + 7) / 8, 256>>>(img, out);
}

// round 6
// speedup vs baseline: 1.3713x; 1.3713x over previous
#include <cuda_runtime.h>
#include <cstdint>

#define BATCH 32
#define NODES 1365         // nodes levels 0..5
#define NODES_ALL 5461     // nodes levels 0..6

static const long long TOK_ELEMS = (long long)BATCH * NODES_ALL * 192; // 33,552,384
static const long long MASK_OFF_ = TOK_ELEMS;
static const long long INFO_OFF_ = TOK_ELEMS + (long long)BATCH * NODES_ALL;

__device__ __constant__ int c_off[8] = {0, 1, 5, 21, 85, 341, 1365, 5461};

// ---- scratch (device globals; no allocations allowed) ----
__device__ float g_sum[BATCH * NODES];
__device__ float g_ssq[BATCH * NODES];
__device__ float g_edge[BATCH * NODES];
__device__ float g_epart[BATCH * 4 * 256];           // per-tile partial edge sums, levels 0..3
__device__ unsigned char g_split[BATCH * NODES];

__device__ __forceinline__ float fast_sqrt(float x) {
    float r;
    asm("sqrt.approx.f32 %0, %1;" : "=f"(r) : "f"(x));
    return r;
}

// ============================================================
// K1: fused gray + level-5 stats + per-level Sobel edge sums.
// One CTA = one 32x32 pixel tile, 256 threads, 4 pixels/thread.
// ============================================================
__global__ void __launch_bounds__(256) k_gray_edge(const float* __restrict__ img) {
    int b = blockIdx.y;
    int ty = blockIdx.x >> 4, tx = blockIdx.x & 15;
    __shared__ float sg[34][36];
    __shared__ float sred[5][32];
    __shared__ float s5[32][2];
    __shared__ float sh_s[32][2], sh_q[32][2];
    int t = threadIdx.x;               // 256
    int py = t >> 3, s8 = t & 7;       // row 0..31, strip 0..7
    int px0 = s8 * 4;
    int Y = ty * 32 + py;
    int X0 = tx * 32 + px0;

    const float* ib = img + (size_t)b * 3 * 262144;
    size_t pidx = (size_t)Y * 512 + X0;
    float4 v0 = *(const float4*)(ib + pidx);
    float4 v1 = *(const float4*)(ib + pidx + 262144);
    float4 v2 = *(const float4*)(ib + pidx + 524288);
    float gr0 = (v0.x + v1.x + v2.x) * (1.0f / 3.0f);
    float gr1 = (v0.y + v1.y + v2.y) * (1.0f / 3.0f);
    float gr2 = (v0.z + v1.z + v2.z) * (1.0f / 3.0f);
    float gr3 = (v0.w + v1.w + v2.w) * (1.0f / 3.0f);
    float s_stat = (v0.x + v1.x + v2.x) + (v0.y + v1.y + v2.y)
                 + (v0.z + v1.z + v2.z) + (v0.w + v1.w + v2.w);
    float q_stat = v0.x * v0.x + v0.y * v0.y + v0.z * v0.z + v0.w * v0.w
                 + v1.x * v1.x + v1.y * v1.y + v1.z * v1.z + v1.w * v1.w
                 + v2.x * v2.x + v2.y * v2.y + v2.z * v2.z + v2.w * v2.w;
    sg[py + 1][px0 + 1] = gr0;
    sg[py + 1][px0 + 2] = gr1;
    sg[py + 1][px0 + 3] = gr2;
    sg[py + 1][px0 + 4] = gr3;

    // halo: 132 perimeter pixels of the 34x34 window
    if (t < 132) {
        int sy, sx;
        if (t < 34)       { sy = 0;           sx = t; }
        else if (t < 68)  { sy = 33;          sx = t - 34; }
        else if (t < 100) { sy = t - 68 + 1;  sx = 0; }
        else              { sy = t - 100 + 1; sx = 33; }
        int gy = ty * 32 - 1 + sy, gx = tx * 32 - 1 + sx;
        float v = 0.0f;
        if (gy >= 0 && gy < 512 && gx >= 0 && gx < 512) {
            size_t q = (size_t)gy * 512 + gx;
            v = (ib[q] + ib[q + 262144] + ib[q + 524288]) * (1.0f / 3.0f);
        }
        sg[sy][sx] = v;
    }
    __syncthreads();

    // 3x6 window covering the 4-pixel strip (+1 halo each side)
    float g[3][6];
    #pragma unroll
    for (int r = 0; r < 3; r++)
        #pragma unroll
        for (int c = 0; c < 6; c++)
            g[r][c] = sg[py + r][px0 + c];

    float lvl[6] = {0, 0, 0, 0, 0, 0};
    #pragma unroll
    for (int i = 0; i < 4; i++) {
        int xg = X0 + i;
        // column sums (x-1 = W, x+1 = E), row sums (y-1 = N, y+1 = S)
        float Et = g[0][i + 2], Em2 = 2.0f * g[1][i + 2], Eb = g[2][i + 2];
        float Wt = g[0][i],     Wm2 = 2.0f * g[1][i],     Wb = g[2][i];
        float Nl = g[0][i], Nm2 = 2.0f * g[0][i + 1], Nr = g[0][i + 2];
        float Sl = g[2][i], Sm2 = 2.0f * g[2][i + 1], Sr = g[2][i + 2];
        float E_nt = Em2 + Eb, E_nb = Et + Em2, E_f = E_nt + Et;
        float W_nt = Wm2 + Wb, W_nb = Wt + Wm2, W_f = W_nt + Wt;
        float N_nl = Nm2 + Nr, N_nr = Nl + Nm2, N_f = N_nl + Nl;
        float S_nl = Sm2 + Sr, S_nr = Sl + Sm2, S_f = S_nl + Sl;
        #pragma unroll
        for (int l = 0; l < 6; l++) {
            int hm = (512 >> l) - 1;
            bool bt = (Y  & hm) == 0, bb = (Y  & hm) == hm;
            bool bl = (xg & hm) == 0, br = (xg & hm) == hm;
            float Ec = bt ? E_nt : (bb ? E_nb : E_f);
            float Wc = bt ? W_nt : (bb ? W_nb : W_f);
            float ex = (br ? 0.0f : Ec) - (bl ? 0.0f : Wc);
            float Nc = bl ? N_nl : (br ? N_nr : N_f);
            float Sc = bl ? S_nl : (br ? S_nr : S_f);
            float ey = (bb ? 0.0f : Sc) - (bt ? 0.0f : Nc);
            lvl[l] += fast_sqrt(ex * ex + ey * ey);
        }
    }

    // levels 0..4: 32-px row sums (reduce over the 8 strips in this row)
    #pragma unroll
    for (int l = 0; l < 5; l++) {
        float v = lvl[l];
        v += __shfl_xor_sync(0xffffffffu, v, 1);
        v += __shfl_xor_sync(0xffffffffu, v, 2);
        v += __shfl_xor_sync(0xffffffffu, v, 4);
        if (s8 == 0) sred[l][py] = v;
    }
    // level 5 + stats: 16-px half-row sums (4-strip groups)
    {
        float v5 = lvl[5], vs = s_stat, vq = q_stat;
        v5 += __shfl_xor_sync(0xffffffffu, v5, 1);
        v5 += __shfl_xor_sync(0xffffffffu, v5, 2);
        vs += __shfl_xor_sync(0xffffffffu, vs, 1);
        vs += __shfl_xor_sync(0xffffffffu, vs, 2);
        vq += __shfl_xor_sync(0xffffffffu, vq, 1);
        vq += __shfl_xor_sync(0xffffffffu, vq, 2);
        if ((s8 & 3) == 0) {
            int h = s8 >> 2;
            s5[py][h] = v5;
            sh_s[py][h] = vs;
            sh_q[py][h] = vq;
        }
    }
    __syncthreads();

    float* eb = g_edge + (size_t)b * NODES;
    if (t < 160) {                     // warps 0..4 finish levels 0..4
        int l = t >> 5, lane = t & 31;
        float w = sred[l][lane];
        #pragma unroll
        for (int o = 16; o; o >>= 1) w += __shfl_xor_sync(0xffffffffu, w, o);
        if (lane == 0) {
            if (l == 4) eb[85 + ty * 16 + tx] = w;
            else        g_epart[(b * 4 + l) * 256 + ty * 16 + tx] = w;
        }
    }
    if (t >= 160 && t < 164) {         // level-5 edge quadrants
        int q = t - 160, qy = q >> 1, qx = q & 1;
        float w = 0.0f;
        #pragma unroll
        for (int r = 0; r < 16; r++) w += s5[qy * 16 + r][qx];
        eb[341 + (ty * 2 + qy) * 32 + (tx * 2 + qx)] = w;
    }
    if (t >= 192 && t < 196) {         // stats quadrants
        int q = t - 192, qy = q >> 1, qx = q & 1;
        float as = 0.0f, aq = 0.0f;
        #pragma unroll
        for (int r = 0; r < 16; r++) {
            as += sh_s[qy * 16 + r][qx];
            aq += sh_q[qy * 16 + r][qx];
        }
        int leaf = (ty * 2 + qy) * 32 + (tx * 2 + qx);
        g_sum[b * NODES + 341 + leaf] = as;
        g_ssq[b * NODES + 341 + leaf] = aq;
    }
}

// ============================================================
// K2: per-batch tree aggregation of sums + edge partial reduce.
// One CTA per batch image.
// ============================================================
__global__ void k_aggregate() {
    int b = blockIdx.x;
    int t = threadIdx.x;  // 256
    __shared__ float sp[256];

    // edge levels 0..3 from per-tile partials
    #pragma unroll
    for (int l = 0; l < 4; l++) {
        sp[t] = g_epart[(b * 4 + l) * 256 + t];
        __syncthreads();
        int n = 1 << l, P = 16 >> l;
        if (t < n * n) {
            int r = t >> l, c = t & (n - 1);
            float acc = 0.0f;
            for (int dy = 0; dy < P; dy++)
                for (int dx = 0; dx < P; dx++)
                    acc += sp[(r * P + dy) * 16 + (c * P + dx)];
            g_edge[(size_t)b * NODES + c_off[l] + t] = acc;
        }
        __syncthreads();
    }

    // sum/ssq quadtree aggregation, levels 4..0
    float* S = g_sum + (size_t)b * NODES;
    float* Q = g_ssq + (size_t)b * NODES;
    for (int l = 4; l >= 0; l--) {
        int n = 1 << l, nn = n << 1;
        int cb = c_off[l + 1], ob = c_off[l];
        for (int i = t; i < n * n; i += blockDim.x) {
            int r = i >> l, c = i & (n - 1);
            int k0 = cb + (2 * r) * nn + 2 * c;
            int k2 = k0 + nn;
            S[ob + i] = S[k0] + S[k0 + 1] + S[k2] + S[k2 + 1];
            Q[ob + i] = Q[k0] + Q[k0 + 1] + Q[k2] + Q[k2 + 1];
        }
        __syncthreads();
    }
}

// ============================================================
// K3: tiled MLP. 64 items per CTA (107KB smem -> 2 CTAs/SM).
// split = (logit >= 0)  (sigmoid(x)>=0.5 <=> x>=0)
// ============================================================
#define MLP_ITEMS 64
#define MLP_SMEM_FLOATS 26752   // 107,008 bytes

__global__ void k_mlp(const float* __restrict__ W1, const float* __restrict__ b1,
                      const float* __restrict__ W2, const float* __restrict__ b2,
                      const float* __restrict__ W3, const float* __restrict__ b3,
                      const float* __restrict__ W4, const float* __restrict__ b4) {
    extern __shared__ float sm[];
    float* sW1 = sm;                 // 768
    float* sb1 = sW1 + 768;          // 128
    float* sW2 = sb1 + 128;          // 8192
    float* sb2 = sW2 + 8192;         // 64
    float* sW3 = sb2 + 64;           // 2048
    float* sb3 = sW3 + 2048;         // 32
    float* sW4 = sb3 + 32;           // 32
    float* sF  = sW4 + 32;           // 6*64
    float* sH1 = sF + 384;           // 64*132
    float* sH2 = sH1 + 64 * 132;     // 64*68
    float* sH3 = sH2 + 64 * 68;      // 64*36

    int t = threadIdx.x;  // 256
    for (int i = t; i < 768; i += 256) sW1[i] = W1[i];
    for (int i = t; i < 128; i += 256) sb1[i] = b1[i];
    for (int i = t; i < 8192; i += 256) sW2[i] = W2[i];
    if (t < 64) sb2[t] = b2[t];
    for (int i = t; i < 2048; i += 256) sW3[i] = W3[i];
    if (t < 32) { sb3[t] = b3[t]; sW4[t] = W4[t]; }
    float bias4 = b4[0];
    int base = blockIdx.x * MLP_ITEMS;

    // phase 1: features
    if (t < MLP_ITEMS) {
        int item = base + t;
        float f0 = 0, f1 = 0, fv = 0, fm = 0, fe = 0;
        if (item < BATCH * NODES) {
            int node = item % NODES;
            int l = node < 1 ? 0 : node < 5 ? 1 : node < 21 ? 2 : node < 85 ? 3 : node < 341 ? 4 : 5;
            int hl = 512 >> l;
            float N = 3.0f * (float)hl * (float)hl;
            float s = g_sum[item], q = g_ssq[item], e = g_edge[item];
            float mean = s / N;
            float var = (q - s * mean) / (N - 1.0f);
            float edge = e / ((float)hl * (float)hl);
            f0 = (float)l; f1 = (float)hl; fv = var; fm = mean; fe = edge;
        }
        sF[0 * 64 + t] = f0;
        sF[1 * 64 + t] = f1;
        sF[2 * 64 + t] = f1;
        sF[3 * 64 + t] = fv;
        sF[4 * 64 + t] = fm;
        sF[5 * 64 + t] = fe;
    }
    __syncthreads();

    // phase 2: H1 = relu(F @ W1 + b1)
    {
        int it = t >> 2;
        int j0 = (t & 3) * 32;
        float f[6];
        #pragma unroll
        for (int i = 0; i < 6; i++) f[i] = sF[i * 64 + it];
        for (int j = j0; j < j0 + 32; j++) {
            float acc = sb1[j];
            #pragma unroll
            for (int i = 0; i < 6; i++) acc += f[i] * sW1[i * 128 + j];
            sH1[it * 132 + j] = fmaxf(acc, 0.0f);
        }
    }
    __syncthreads();

    // phase 3: H2 = relu(H1 @ W2 + b2)
    {
        int it0 = (t >> 3) * 2;
        int j0 = (t & 7) * 8;
        float acc[2][8];
        #pragma unroll
        for (int m = 0; m < 2; m++)
            #pragma unroll
            for (int j = 0; j < 8; j++) acc[m][j] = sb2[j0 + j];
        for (int i = 0; i < 128; i += 4) {
            float a[2][4];
            #pragma unroll
            for (int m = 0; m < 2; m++) {
                float4 v = *(const float4*)&sH1[(it0 + m) * 132 + i];
                a[m][0] = v.x; a[m][1] = v.y; a[m][2] = v.z; a[m][3] = v.w;
            }
            #pragma unroll
            for (int k = 0; k < 4; k++) {
                float4 w0 = *(const float4*)&sW2[(i + k) * 64 + j0];
                float4 w1 = *(const float4*)&sW2[(i + k) * 64 + j0 + 4];
                float wv[8] = {w0.x, w0.y, w0.z, w0.w, w1.x, w1.y, w1.z, w1.w};
                #pragma unroll
                for (int m = 0; m < 2; m++)
                    #pragma unroll
                    for (int j = 0; j < 8; j++) acc[m][j] += a[m][k] * wv[j];
            }
        }
        #pragma unroll
        for (int m = 0; m < 2; m++)
            #pragma unroll
            for (int j = 0; j < 8; j++)
                sH2[(it0 + m) * 68 + j0 + j] = fmaxf(acc[m][j], 0.0f);
    }
    __syncthreads();

    // phase 4: H3 = relu(H2 @ W3 + b3)
    {
        int it = t >> 2;
        int j0 = (t & 3) * 8;
        float acc[8];
        #pragma unroll
        for (int j = 0; j < 8; j++) acc[j] = sb3[j0 + j];
        for (int i = 0; i < 64; i += 4) {
            float4 v = *(const float4*)&sH2[it * 68 + i];
            float a[4] = {v.x, v.y, v.z, v.w};
            #pragma unroll
            for (int k = 0; k < 4; k++) {
                float4 w0 = *(const float4*)&sW3[(i + k) * 32 + j0];
                float4 w1 = *(const float4*)&sW3[(i + k) * 32 + j0 + 4];
                float wv[8] = {w0.x, w0.y, w0.z, w0.w, w1.x, w1.y, w1.z, w1.w};
                #pragma unroll
                for (int j = 0; j < 8; j++) acc[j] += a[k] * wv[j];
            }
        }
        #pragma unroll
        for (int j = 0; j < 8; j++)
            sH3[it * 36 + j0 + j] = fmaxf(acc[j], 0.0f);
    }
    __syncthreads();

    // phase 5: logit sign
    if (t < MLP_ITEMS) {
        int item = base + t;
        float acc = bias4;
        #pragma unroll
        for (int k = 0; k < 32; k += 4) {
            float4 h = *(const float4*)&sH3[t * 36 + k];
            float4 w = *(const float4*)&sW4[k];
            acc += h.x * w.x + h.y * w.y + h.z * w.z + h.w * w.w;
        }
        if (item < BATCH * NODES) g_split[item] = (unsigned char)(acc >= 0.0f);
    }
}

// ============================================================
// K4: write tokens (Hilbert-DFS order), mask, level_info.
// Mask computed inline from <=6 ancestor split flags (uniform loads).
// Masked-out tokens are exact zeros -> skip the image read entirely.
// ============================================================
__global__ void k_write(const float* __restrict__ img, float* __restrict__ out) {
    int gw = blockIdx.x * 8 + (threadIdx.x >> 5);
    if (gw >= BATCH * NODES_ALL) return;
    int lane = threadIdx.x & 31;
    int b = gw / NODES_ALL;
    int p = gw - b * NODES_ALL;

    // decode DFS position -> (level,row,col,path)
    int level = 0, row = 0, col = 0, pp = p, plen = 0;
    unsigned pathbits = 0;
    while (pp > 0) {
        pp--;
        int s = ((1 << (2 * (6 - level))) - 1) / 3;   // child subtree size
        int ci = pp / s;
        pp -= ci * s;
        int q = (0x3102 >> (ci * 4)) & 0xF;           // HILBERT = [2,0,1,3]
        row = 2 * row + (q >> 1);
        col = 2 * col + (q & 1);
        pathbits |= (unsigned)q << (3 * plen);
        plen++;
        level++;
    }

    // mask from ancestor split chain
    const unsigned char* sp = g_split + (size_t)b * NODES;
    bool alive = true;
    for (int j = 0; j < level; j++) {
        int idx = c_off[j] + ((row >> (level - j)) << j) + (col >> (level - j));
        alive = alive && (sp[idx] != 0);
    }
    float m;
    if (level < 6) m = (alive && sp[c_off[level] + (row << level) + col] == 0) ? 1.0f : 0.0f;
    else           m = alive ? 1.0f : 0.0f;

    float* o = out + (size_t)gw * 192;
    if (m != 0.0f) {
        int hl = 512 >> level;
        int Y0 = row * hl + ((hl - 8) >> 1);
        int X0 = col * hl + ((hl - 8) >> 1);
        if (lane < 24) {
            int c = lane >> 3, r = lane & 7;
            const float* src = img + ((size_t)(b * 3 + c) * 512 + (size_t)(Y0 + r)) * 512 + X0;
            float4 v0 = __ldg((const float4*)src);
            float4 v1 = __ldg((const float4*)(src + 4));
            float* dst = o + c * 64 + r * 8;
            *(float4*)dst = v0;
            *(float4*)(dst + 4) = v1;
        }
    } else {
        float4 z = make_float4(0.0f, 0.0f, 0.0f, 0.0f);
        if (lane < 24) {
            float* dst = o + lane * 8;
            *(float4*)dst = z;
            *(float4*)(dst + 4) = z;
        }
    }
    if (lane == 24) out[MASK_OFF_ + (size_t)gw] = m;
    if (b == 0 && lane >= 25 && lane < 27) {
        int base16 = (lane - 25) * 8;
        #pragma unroll
        for (int k = 0; k < 8; k++) {
            int slot = base16 + k;
            float v = 0.0f;
            if (slot == 0) v = (float)level;
            else if (slot - 1 < plen) v = (float)((pathbits >> (3 * (slot - 1))) & 7);
            out[INFO_OFF_ + (size_t)p * 16 + slot] = v;
        }
    }
}

// ============================================================
extern "C" void kernel_launch(void* const* d_in, const int* in_sizes, int n_in,
                              void* d_out, int out_size) {
    const float* img = (const float*)d_in[0];
    const float* W1 = (const float*)d_in[1];
    const float* b1 = (const float*)d_in[2];
    const float* W2 = (const float*)d_in[3];
    const float* b2 = (const float*)d_in[4];
    const float* W3 = (const float*)d_in[5];
    const float* b3 = (const float*)d_in[6];
    const float* W4 = (const float*)d_in[7];
    const float* b4 = (const float*)d_in[8];
    float* out = (float*)d_out;

    cudaFuncSetAttribute(k_mlp, cudaFuncAttributeMaxDynamicSharedMemorySize,
                         MLP_SMEM_FLOATS * (int)sizeof(float));

    k_gray_edge<<<dim3(256, BATCH), 256>>>(img);
    k_aggregate<<<BATCH, 256>>>();
    int mlp_blocks = (BATCH * NODES + MLP_ITEMS - 1) / MLP_ITEMS;  // 683
    k_mlp<<<mlp_blocks, 256, MLP_SMEM_FLOATS * sizeof(float)>>>(W1, b1, W2, b2, W3, b3, W4, b4);
    k_write<<<(BATCH * NODES_ALL + 7) / 8, 256>>>(img, out);
}

// round 7
// speedup vs baseline: 1.4783x; 1.0781x over previous
#include <cuda_runtime.h>
#include <cstdint>

#define BATCH 32
#define NODES 1365         // nodes levels 0..5
#define NODES_ALL 5461     // nodes levels 0..6

static const long long TOK_ELEMS = (long long)BATCH * NODES_ALL * 192; // 33,552,384
static const long long MASK_OFF_ = TOK_ELEMS;
static const long long INFO_OFF_ = TOK_ELEMS + (long long)BATCH * NODES_ALL;

__device__ __constant__ int c_off[8] = {0, 1, 5, 21, 85, 341, 1365, 5461};

// ---- scratch (device globals; no allocations allowed) ----
__device__ float g_sum[BATCH * NODES];
__device__ float g_ssq[BATCH * NODES];
__device__ float g_edge[BATCH * NODES];
__device__ float g_epart[BATCH * 4 * 256];           // per-tile partial edge sums, levels 0..3
__device__ unsigned char g_split[BATCH * NODES];
__device__ uint2 g_tbl[NODES_ALL];                   // DFS decode table

__device__ __forceinline__ float fast_sqrt(float x) {
    float r;
    asm("sqrt.approx.f32 %0, %1;" : "=f"(r) : "f"(x));
    return r;
}

__device__ __forceinline__ void st_cs_f4(float* p, float4 v) {
    asm volatile("st.global.cs.v4.f32 [%0], {%1,%2,%3,%4};"
                 :: "l"(p), "f"(v.x), "f"(v.y), "f"(v.z), "f"(v.w) : "memory");
}

// ============================================================
// K1: fused gray + level-5 stats + per-level Sobel edge sums.
// One CTA = one 32x32 pixel tile, 256 threads, 4 pixels/thread.
// ============================================================
__global__ void __launch_bounds__(256) k_gray_edge(const float* __restrict__ img) {
    int b = blockIdx.y;
    int ty = blockIdx.x >> 4, tx = blockIdx.x & 15;
    __shared__ float sg[34][36];
    __shared__ float sred[5][32];
    __shared__ float s5[32][2];
    __shared__ float sh_s[32][2], sh_q[32][2];
    int t = threadIdx.x;               // 256
    int py = t >> 3, s8 = t & 7;       // row 0..31, strip 0..7
    int px0 = s8 * 4;
    int Y = ty * 32 + py;
    int X0 = tx * 32 + px0;

    const float* ib = img + (size_t)b * 3 * 262144;
    size_t pidx = (size_t)Y * 512 + X0;
    float4 v0 = *(const float4*)(ib + pidx);
    float4 v1 = *(const float4*)(ib + pidx + 262144);
    float4 v2 = *(const float4*)(ib + pidx + 524288);
    float gr0 = (v0.x + v1.x + v2.x) * (1.0f / 3.0f);
    float gr1 = (v0.y + v1.y + v2.y) * (1.0f / 3.0f);
    float gr2 = (v0.z + v1.z + v2.z) * (1.0f / 3.0f);
    float gr3 = (v0.w + v1.w + v2.w) * (1.0f / 3.0f);
    float s_stat = (v0.x + v1.x + v2.x) + (v0.y + v1.y + v2.y)
                 + (v0.z + v1.z + v2.z) + (v0.w + v1.w + v2.w);
    float q_stat = v0.x * v0.x + v0.y * v0.y + v0.z * v0.z + v0.w * v0.w
                 + v1.x * v1.x + v1.y * v1.y + v1.z * v1.z + v1.w * v1.w
                 + v2.x * v2.x + v2.y * v2.y + v2.z * v2.z + v2.w * v2.w;
    sg[py + 1][px0 + 1] = gr0;
    sg[py + 1][px0 + 2] = gr1;
    sg[py + 1][px0 + 3] = gr2;
    sg[py + 1][px0 + 4] = gr3;

    // halo: 132 perimeter pixels of the 34x34 window
    if (t < 132) {
        int sy, sx;
        if (t < 34)       { sy = 0;           sx = t; }
        else if (t < 68)  { sy = 33;          sx = t - 34; }
        else if (t < 100) { sy = t - 68 + 1;  sx = 0; }
        else              { sy = t - 100 + 1; sx = 33; }
        int gy = ty * 32 - 1 + sy, gx = tx * 32 - 1 + sx;
        float v = 0.0f;
        if (gy >= 0 && gy < 512 && gx >= 0 && gx < 512) {
            size_t q = (size_t)gy * 512 + gx;
            v = (ib[q] + ib[q + 262144] + ib[q + 524288]) * (1.0f / 3.0f);
        }
        sg[sy][sx] = v;
    }
    __syncthreads();

    // 3x6 window covering the 4-pixel strip (+1 halo each side)
    float g[3][6];
    #pragma unroll
    for (int r = 0; r < 3; r++)
        #pragma unroll
        for (int c = 0; c < 6; c++)
            g[r][c] = sg[py + r][px0 + c];

    float lvl[6] = {0, 0, 0, 0, 0, 0};
    #pragma unroll
    for (int i = 0; i < 4; i++) {
        int xg = X0 + i;
        float Et = g[0][i + 2], Em2 = 2.0f * g[1][i + 2], Eb = g[2][i + 2];
        float Wt = g[0][i],     Wm2 = 2.0f * g[1][i],     Wb = g[2][i];
        float Nl = g[0][i], Nm2 = 2.0f * g[0][i + 1], Nr = g[0][i + 2];
        float Sl = g[2][i], Sm2 = 2.0f * g[2][i + 1], Sr = g[2][i + 2];
        float E_nt = Em2 + Eb, E_nb = Et + Em2, E_f = E_nt + Et;
        float W_nt = Wm2 + Wb, W_nb = Wt + Wm2, W_f = W_nt + Wt;
        float N_nl = Nm2 + Nr, N_nr = Nl + Nm2, N_f = N_nl + Nl;
        float S_nl = Sm2 + Sr, S_nr = Sl + Sm2, S_f = S_nl + Sl;
        #pragma unroll
        for (int l = 0; l < 6; l++) {
            int hm = (512 >> l) - 1;
            bool bt = (Y  & hm) == 0, bb = (Y  & hm) == hm;
            bool bl = (xg & hm) == 0, br = (xg & hm) == hm;
            float Ec = bt ? E_nt : (bb ? E_nb : E_f);
            float Wc = bt ? W_nt : (bb ? W_nb : W_f);
            float ex = (br ? 0.0f : Ec) - (bl ? 0.0f : Wc);
            float Nc = bl ? N_nl : (br ? N_nr : N_f);
            float Sc = bl ? S_nl : (br ? S_nr : S_f);
            float ey = (bb ? 0.0f : Sc) - (bt ? 0.0f : Nc);
            lvl[l] += fast_sqrt(ex * ex + ey * ey);
        }
    }

    // levels 0..4: 32-px row sums (reduce over the 8 strips in this row)
    #pragma unroll
    for (int l = 0; l < 5; l++) {
        float v = lvl[l];
        v += __shfl_xor_sync(0xffffffffu, v, 1);
        v += __shfl_xor_sync(0xffffffffu, v, 2);
        v += __shfl_xor_sync(0xffffffffu, v, 4);
        if (s8 == 0) sred[l][py] = v;
    }
    // level 5 + stats: 16-px half-row sums (4-strip groups)
    {
        float v5 = lvl[5], vs = s_stat, vq = q_stat;
        v5 += __shfl_xor_sync(0xffffffffu, v5, 1);
        v5 += __shfl_xor_sync(0xffffffffu, v5, 2);
        vs += __shfl_xor_sync(0xffffffffu, vs, 1);
        vs += __shfl_xor_sync(0xffffffffu, vs, 2);
        vq += __shfl_xor_sync(0xffffffffu, vq, 1);
        vq += __shfl_xor_sync(0xffffffffu, vq, 2);
        if ((s8 & 3) == 0) {
            int h = s8 >> 2;
            s5[py][h] = v5;
            sh_s[py][h] = vs;
            sh_q[py][h] = vq;
        }
    }
    __syncthreads();

    float* eb = g_edge + (size_t)b * NODES;
    if (t < 160) {                     // warps 0..4 finish levels 0..4
        int l = t >> 5, lane = t & 31;
        float w = sred[l][lane];
        #pragma unroll
        for (int o = 16; o; o >>= 1) w += __shfl_xor_sync(0xffffffffu, w, o);
        if (lane == 0) {
            if (l == 4) eb[85 + ty * 16 + tx] = w;
            else        g_epart[(b * 4 + l) * 256 + ty * 16 + tx] = w;
        }
    }
    if (t >= 160 && t < 164) {         // level-5 edge quadrants
        int q = t - 160, qy = q >> 1, qx = q & 1;
        float w = 0.0f;
        #pragma unroll
        for (int r = 0; r < 16; r++) w += s5[qy * 16 + r][qx];
        eb[341 + (ty * 2 + qy) * 32 + (tx * 2 + qx)] = w;
    }
    if (t >= 192 && t < 196) {         // stats quadrants
        int q = t - 192, qy = q >> 1, qx = q & 1;
        float as = 0.0f, aq = 0.0f;
        #pragma unroll
        for (int r = 0; r < 16; r++) {
            as += sh_s[qy * 16 + r][qx];
            aq += sh_q[qy * 16 + r][qx];
        }
        int leaf = (ty * 2 + qy) * 32 + (tx * 2 + qx);
        g_sum[b * NODES + 341 + leaf] = as;
        g_ssq[b * NODES + 341 + leaf] = aq;
    }
}

// ============================================================
// K2: per-batch tree aggregation + DFS decode table build.
// One CTA per batch image; CTA b also decodes DFS slots b*256..b*256+255.
// ============================================================
__global__ void k_aggregate() {
    int b = blockIdx.x;
    int t = threadIdx.x;  // 256
    __shared__ float sp[256];

    // ---- DFS decode table (batch-independent; 8192 threads cover 5461)
    {
        int p = b * 256 + t;
        if (p < NODES_ALL) {
            int level = 0, row = 0, col = 0, pp = p, plen = 0;
            unsigned pathbits = 0;
            #pragma unroll
            for (int L = 0; L < 6; L++) {
                if (pp > 0) {
                    pp--;
                    const int s = ((1 << (2 * (6 - L))) - 1) / 3;  // 1365,341,85,21,5,1
                    int ci = pp / s;
                    pp -= ci * s;
                    int q = (0x3102 >> (ci * 4)) & 0xF;            // HILBERT=[2,0,1,3]
                    row = 2 * row + (q >> 1);
                    col = 2 * col + (q & 1);
                    pathbits |= (unsigned)q << (3 * plen);
                    plen++;
                    level++;
                }
            }
            int node = c_off[level] + (row << level) + col;
            uint2 w;
            w.x = (unsigned)node | ((unsigned)level << 16) |
                  ((unsigned)row << 19) | ((unsigned)col << 25);
            w.y = pathbits | ((unsigned)plen << 24);
            g_tbl[p] = w;
        }
    }

    // edge levels 0..3 from per-tile partials
    #pragma unroll
    for (int l = 0; l < 4; l++) {
        sp[t] = g_epart[(b * 4 + l) * 256 + t];
        __syncthreads();
        int n = 1 << l, P = 16 >> l;
        if (t < n * n) {
            int r = t >> l, c = t & (n - 1);
            float acc = 0.0f;
            for (int dy = 0; dy < P; dy++)
                for (int dx = 0; dx < P; dx++)
                    acc += sp[(r * P + dy) * 16 + (c * P + dx)];
            g_edge[(size_t)b * NODES + c_off[l] + t] = acc;
        }
        __syncthreads();
    }

    // sum/ssq quadtree aggregation, levels 4..0
    float* S = g_sum + (size_t)b * NODES;
    float* Q = g_ssq + (size_t)b * NODES;
    for (int l = 4; l >= 0; l--) {
        int n = 1 << l, nn = n << 1;
        int cb = c_off[l + 1], ob = c_off[l];
        for (int i = t; i < n * n; i += blockDim.x) {
            int r = i >> l, c = i & (n - 1);
            int k0 = cb + (2 * r) * nn + 2 * c;
            int k2 = k0 + nn;
            S[ob + i] = S[k0] + S[k0 + 1] + S[k2] + S[k2 + 1];
            Q[ob + i] = Q[k0] + Q[k0 + 1] + Q[k2] + Q[k2 + 1];
        }
        __syncthreads();
    }
}

// ============================================================
// K3: tiled MLP. 64 items per CTA (107KB smem -> 2 CTAs/SM).
// split = (logit >= 0)  (sigmoid(x)>=0.5 <=> x>=0)
// ============================================================
#define MLP_ITEMS 64
#define MLP_SMEM_FLOATS 26752   // 107,008 bytes

__global__ void k_mlp(const float* __restrict__ W1, const float* __restrict__ b1,
                      const float* __restrict__ W2, const float* __restrict__ b2,
                      const float* __restrict__ W3, const float* __restrict__ b3,
                      const float* __restrict__ W4, const float* __restrict__ b4) {
    extern __shared__ float sm[];
    float* sW1 = sm;                 // 768
    float* sb1 = sW1 + 768;          // 128
    float* sW2 = sb1 + 128;          // 8192
    float* sb2 = sW2 + 8192;         // 64
    float* sW3 = sb2 + 64;           // 2048
    float* sb3 = sW3 + 2048;         // 32
    float* sW4 = sb3 + 32;           // 32
    float* sF  = sW4 + 32;           // 6*64
    float* sH1 = sF + 384;           // 64*132
    float* sH2 = sH1 + 64 * 132;     // 64*68
    float* sH3 = sH2 + 64 * 68;      // 64*36

    int t = threadIdx.x;  // 256
    for (int i = t; i < 768; i += 256) sW1[i] = W1[i];
    for (int i = t; i < 128; i += 256) sb1[i] = b1[i];
    for (int i = t; i < 8192; i += 256) sW2[i] = W2[i];
    if (t < 64) sb2[t] = b2[t];
    for (int i = t; i < 2048; i += 256) sW3[i] = W3[i];
    if (t < 32) { sb3[t] = b3[t]; sW4[t] = W4[t]; }
    float bias4 = b4[0];
    int base = blockIdx.x * MLP_ITEMS;

    // phase 1: features
    if (t < MLP_ITEMS) {
        int item = base + t;
        float f0 = 0, f1 = 0, fv = 0, fm = 0, fe = 0;
        if (item < BATCH * NODES) {
            int node = item % NODES;
            int l = node < 1 ? 0 : node < 5 ? 1 : node < 21 ? 2 : node < 85 ? 3 : node < 341 ? 4 : 5;
            int hl = 512 >> l;
            float N = 3.0f * (float)hl * (float)hl;
            float s = g_sum[item], q = g_ssq[item], e = g_edge[item];
            float mean = s / N;
            float var = (q - s * mean) / (N - 1.0f);
            float edge = e / ((float)hl * (float)hl);
            f0 = (float)l; f1 = (float)hl; fv = var; fm = mean; fe = edge;
        }
        sF[0 * 64 + t] = f0;
        sF[1 * 64 + t] = f1;
        sF[2 * 64 + t] = f1;
        sF[3 * 64 + t] = fv;
        sF[4 * 64 + t] = fm;
        sF[5 * 64 + t] = fe;
    }
    __syncthreads();

    // phase 2: H1 = relu(F @ W1 + b1)
    {
        int it = t >> 2;
        int j0 = (t & 3) * 32;
        float f[6];
        #pragma unroll
        for (int i = 0; i < 6; i++) f[i] = sF[i * 64 + it];
        for (int j = j0; j < j0 + 32; j++) {
            float acc = sb1[j];
            #pragma unroll
            for (int i = 0; i < 6; i++) acc += f[i] * sW1[i * 128 + j];
            sH1[it * 132 + j] = fmaxf(acc, 0.0f);
        }
    }
    __syncthreads();

    // phase 3: H2 = relu(H1 @ W2 + b2)
    {
        int it0 = (t >> 3) * 2;
        int j0 = (t & 7) * 8;
        float acc[2][8];
        #pragma unroll
        for (int m = 0; m < 2; m++)
            #pragma unroll
            for (int j = 0; j < 8; j++) acc[m][j] = sb2[j0 + j];
        for (int i = 0; i < 128; i += 4) {
            float a[2][4];
            #pragma unroll
            for (int m = 0; m < 2; m++) {
                float4 v = *(const float4*)&sH1[(it0 + m) * 132 + i];
                a[m][0] = v.x; a[m][1] = v.y; a[m][2] = v.z; a[m][3] = v.w;
            }
            #pragma unroll
            for (int k = 0; k < 4; k++) {
                float4 w0 = *(const float4*)&sW2[(i + k) * 64 + j0];
                float4 w1 = *(const float4*)&sW2[(i + k) * 64 + j0 + 4];
                float wv[8] = {w0.x, w0.y, w0.z, w0.w, w1.x, w1.y, w1.z, w1.w};
                #pragma unroll
                for (int m = 0; m < 2; m++)
                    #pragma unroll
                    for (int j = 0; j < 8; j++) acc[m][j] += a[m][k] * wv[j];
            }
        }
        #pragma unroll
        for (int m = 0; m < 2; m++)
            #pragma unroll
            for (int j = 0; j < 8; j++)
                sH2[(it0 + m) * 68 + j0 + j] = fmaxf(acc[m][j], 0.0f);
    }
    __syncthreads();

    // phase 4: H3 = relu(H2 @ W3 + b3)
    {
        int it = t >> 2;
        int j0 = (t & 3) * 8;
        float acc[8];
        #pragma unroll
        for (int j = 0; j < 8; j++) acc[j] = sb3[j0 + j];
        for (int i = 0; i < 64; i += 4) {
            float4 v = *(const float4*)&sH2[it * 68 + i];
            float a[4] = {v.x, v.y, v.z, v.w};
            #pragma unroll
            for (int k = 0; k < 4; k++) {
                float4 w0 = *(const float4*)&sW3[(i + k) * 32 + j0];
                float4 w1 = *(const float4*)&sW3[(i + k) * 32 + j0 + 4];
                float wv[8] = {w0.x, w0.y, w0.z, w0.w, w1.x, w1.y, w1.z, w1.w};
                #pragma unroll
                for (int j = 0; j < 8; j++) acc[j] += a[k] * wv[j];
            }
        }
        #pragma unroll
        for (int j = 0; j < 8; j++)
            sH3[it * 36 + j0 + j] = fmaxf(acc[j], 0.0f);
    }
    __syncthreads();

    // phase 5: logit sign
    if (t < MLP_ITEMS) {
        int item = base + t;
        float acc = bias4;
        #pragma unroll
        for (int k = 0; k < 32; k += 4) {
            float4 h = *(const float4*)&sH3[t * 36 + k];
            float4 w = *(const float4*)&sW4[k];
            acc += h.x * w.x + h.y * w.y + h.z * w.z + h.w * w.w;
        }
        if (item < BATCH * NODES) g_split[item] = (unsigned char)(acc >= 0.0f);
    }
}

// ============================================================
// K4: write tokens (Hilbert-DFS order), mask, level_info.
// DFS decode replaced by table lookup; streaming stores for tokens.
// ============================================================
__global__ void k_write(const float* __restrict__ img, float* __restrict__ out) {
    int gw = blockIdx.x * 8 + (threadIdx.x >> 5);
    if (gw >= BATCH * NODES_ALL) return;
    int lane = threadIdx.x & 31;
    int b = gw / NODES_ALL;
    int p = gw - b * NODES_ALL;

    uint2 w = g_tbl[p];
    int node  = w.x & 0xFFFF;
    int level = (w.x >> 16) & 7;
    int row   = (w.x >> 19) & 63;
    int col   = (w.x >> 25) & 63;
    unsigned pathbits = w.y & 0xFFFFFF;
    int plen = (int)(w.y >> 24);

    // mask from ancestor split chain
    const unsigned char* sp = g_split + (size_t)b * NODES;
    bool alive = true;
    #pragma unroll
    for (int j = 0; j < 6; j++) {
        if (j < level) {
            int idx = c_off[j] + ((row >> (level - j)) << j) + (col >> (level - j));
            alive = alive && (sp[idx] != 0);
        }
    }
    float m;
    if (level < 6) m = (alive && sp[node] == 0) ? 1.0f : 0.0f;
    else           m = alive ? 1.0f : 0.0f;

    float* o = out + (size_t)gw * 192;
    if (m != 0.0f) {
        int hl = 512 >> level;
        int Y0 = row * hl + ((hl - 8) >> 1);
        int X0 = col * hl + ((hl - 8) >> 1);
        if (lane < 24) {
            int c = lane >> 3, r = lane & 7;
            const float* src = img + ((size_t)(b * 3 + c) * 512 + (size_t)(Y0 + r)) * 512 + X0;
            float4 v0 = __ldg((const float4*)src);
            float4 v1 = __ldg((const float4*)(src + 4));
            float* dst = o + c * 64 + r * 8;
            st_cs_f4(dst, v0);
            st_cs_f4(dst + 4, v1);
        }
    } else {
        float4 z = make_float4(0.0f, 0.0f, 0.0f, 0.0f);
        if (lane < 24) {
            float* dst = o + lane * 8;
            st_cs_f4(dst, z);
            st_cs_f4(dst + 4, z);
        }
    }
    if (lane == 24) out[MASK_OFF_ + (size_t)gw] = m;
    if (b == 0 && lane >= 25 && lane < 27) {
        int base16 = (lane - 25) * 8;
        #pragma unroll
        for (int k = 0; k < 8; k++) {
            int slot = base16 + k;
            float v = 0.0f;
            if (slot == 0) v = (float)level;
            else if (slot - 1 < plen) v = (float)((pathbits >> (3 * (slot - 1))) & 7);
            out[INFO_OFF_ + (size_t)p * 16 + slot] = v;
        }
    }
}

// ============================================================
extern "C" void kernel_launch(void* const* d_in, const int* in_sizes, int n_in,
                              void* d_out, int out_size) {
    const float* img = (const float*)d_in[0];
    const float* W1 = (const float*)d_in[1];
    const float* b1 = (const float*)d_in[2];
    const float* W2 = (const float*)d_in[3];
    const float* b2 = (const float*)d_in[4];
    const float* W3 = (const float*)d_in[5];
    const float* b3 = (const float*)d_in[6];
    const float* W4 = (const float*)d_in[7];
    const float* b4 = (const float*)d_in[8];
    float* out = (float*)d_out;

    cudaFuncSetAttribute(k_mlp, cudaFuncAttributeMaxDynamicSharedMemorySize,
                         MLP_SMEM_FLOATS * (int)sizeof(float));

    k_gray_edge<<<dim3(256, BATCH), 256>>>(img);
    k_aggregate<<<BATCH, 256>>>();
    int mlp_blocks = (BATCH * NODES + MLP_ITEMS - 1) / MLP_ITEMS;  // 683
    k_mlp<<<mlp_blocks, 256, MLP_SMEM_FLOATS * sizeof(float)>>>(W1, b1, W2, b2, W3, b3, W4, b4);
    k_write<<<(BATCH * NODES_ALL + 7) / 8, 256>>>(img, out);
}

// round 9
// speedup vs baseline: 1.5358x; 1.0388x over previous
#include <cuda_runtime.h>
#include <cstdint>

#define BATCH 32
#define NODES 1365         // nodes levels 0..5
#define NODES_ALL 5461     // nodes levels 0..6

static const long long TOK_ELEMS = (long long)BATCH * NODES_ALL * 192; // 33,552,384
static const long long MASK_OFF_ = TOK_ELEMS;
static const long long INFO_OFF_ = TOK_ELEMS + (long long)BATCH * NODES_ALL;

__device__ __constant__ int c_off[8] = {0, 1, 5, 21, 85, 341, 1365, 5461};

// ---- scratch (device globals; no allocations allowed) ----
__device__ float g_sum[BATCH * NODES];
__device__ float g_ssq[BATCH * NODES];
__device__ float g_edge[BATCH * NODES];
__device__ float g_epart[BATCH * 4 * 256];           // per-tile partial edge sums, levels 0..3
__device__ unsigned char g_split[BATCH * NODES];
__device__ uint2 g_tbl[NODES_ALL];                   // DFS decode table
__device__ float g_maskf[BATCH * NODES_ALL];         // per-(b,dfs) mask

__device__ __forceinline__ float fast_sqrt(float x) {
    float r;
    asm("sqrt.approx.f32 %0, %1;" : "=f"(r) : "f"(x));
    return r;
}

__device__ __forceinline__ void st_cs_f4(float* p, float4 v) {
    asm volatile("st.global.cs.v4.f32 [%0], {%1,%2,%3,%4};"
                 :: "l"(p), "f"(v.x), "f"(v.y), "f"(v.z), "f"(v.w) : "memory");
}

// ============================================================
// K1: fused gray + level-5 stats + per-level Sobel edge sums.
// One CTA = one 32x32 pixel tile, 256 threads, 4 pixels/thread.
// ============================================================
__global__ void __launch_bounds__(256) k_gray_edge(const float* __restrict__ img) {
    int b = blockIdx.y;
    int ty = blockIdx.x >> 4, tx = blockIdx.x & 15;
    __shared__ float sg[34][36];
    __shared__ float sred[5][32];
    __shared__ float s5[32][2];
    __shared__ float sh_s[32][2], sh_q[32][2];
    int t = threadIdx.x;               // 256
    int py = t >> 3, s8 = t & 7;       // row 0..31, strip 0..7
    int px0 = s8 * 4;
    int Y = ty * 32 + py;
    int X0 = tx * 32 + px0;

    const float* ib = img + (size_t)b * 3 * 262144;
    size_t pidx = (size_t)Y * 512 + X0;
    float4 v0 = *(const float4*)(ib + pidx);
    float4 v1 = *(const float4*)(ib + pidx + 262144);
    float4 v2 = *(const float4*)(ib + pidx + 524288);
    float gr0 = (v0.x + v1.x + v2.x) * (1.0f / 3.0f);
    float gr1 = (v0.y + v1.y + v2.y) * (1.0f / 3.0f);
    float gr2 = (v0.z + v1.z + v2.z) * (1.0f / 3.0f);
    float gr3 = (v0.w + v1.w + v2.w) * (1.0f / 3.0f);
    float s_stat = (v0.x + v1.x + v2.x) + (v0.y + v1.y + v2.y)
                 + (v0.z + v1.z + v2.z) + (v0.w + v1.w + v2.w);
    float q_stat = v0.x * v0.x + v0.y * v0.y + v0.z * v0.z + v0.w * v0.w
                 + v1.x * v1.x + v1.y * v1.y + v1.z * v1.z + v1.w * v1.w
                 + v2.x * v2.x + v2.y * v2.y + v2.z * v2.z + v2.w * v2.w;
    sg[py + 1][px0 + 1] = gr0;
    sg[py + 1][px0 + 2] = gr1;
    sg[py + 1][px0 + 3] = gr2;
    sg[py + 1][px0 + 4] = gr3;

    // halo: 132 perimeter pixels of the 34x34 window
    if (t < 132) {
        int sy, sx;
        if (t < 34)       { sy = 0;           sx = t; }
        else if (t < 68)  { sy = 33;          sx = t - 34; }
        else if (t < 100) { sy = t - 68 + 1;  sx = 0; }
        else              { sy = t - 100 + 1; sx = 33; }
        int gy = ty * 32 - 1 + sy, gx = tx * 32 - 1 + sx;
        float v = 0.0f;
        if (gy >= 0 && gy < 512 && gx >= 0 && gx < 512) {
            size_t q = (size_t)gy * 512 + gx;
            v = (ib[q] + ib[q + 262144] + ib[q + 524288]) * (1.0f / 3.0f);
        }
        sg[sy][sx] = v;
    }
    __syncthreads();

    // 3x6 window covering the 4-pixel strip (+1 halo each side)
    float g[3][6];
    #pragma unroll
    for (int r = 0; r < 3; r++)
        #pragma unroll
        for (int c = 0; c < 6; c++)
            g[r][c] = sg[py + r][px0 + c];

    float lvl[6] = {0, 0, 0, 0, 0, 0};
    #pragma unroll
    for (int i = 0; i < 4; i++) {
        int xg = X0 + i;
        float Et = g[0][i + 2], Em2 = 2.0f * g[1][i + 2], Eb = g[2][i + 2];
        float Wt = g[0][i],     Wm2 = 2.0f * g[1][i],     Wb = g[2][i];
        float Nl = g[0][i], Nm2 = 2.0f * g[0][i + 1], Nr = g[0][i + 2];
        float Sl = g[2][i], Sm2 = 2.0f * g[2][i + 1], Sr = g[2][i + 2];
        float E_nt = Em2 + Eb, E_nb = Et + Em2, E_f = E_nt + Et;
        float W_nt = Wm2 + Wb, W_nb = Wt + Wm2, W_f = W_nt + Wt;
        float N_nl = Nm2 + Nr, N_nr = Nl + Nm2, N_f = N_nl + Nl;
        float S_nl = Sm2 + Sr, S_nr = Sl + Sm2, S_f = S_nl + Sl;
        #pragma unroll
        for (int l = 0; l < 6; l++) {
            int hm = (512 >> l) - 1;
            bool bt = (Y  & hm) == 0, bb = (Y  & hm) == hm;
            bool bl = (xg & hm) == 0, br = (xg & hm) == hm;
            float Ec = bt ? E_nt : (bb ? E_nb : E_f);
            float Wc = bt ? W_nt : (bb ? W_nb : W_f);
            float ex = (br ? 0.0f : Ec) - (bl ? 0.0f : Wc);
            float Nc = bl ? N_nl : (br ? N_nr : N_f);
            float Sc = bl ? S_nl : (br ? S_nr : S_f);
            float ey = (bb ? 0.0f : Sc) - (bt ? 0.0f : Nc);
            lvl[l] += fast_sqrt(ex * ex + ey * ey);
        }
    }

    // levels 0..4: 32-px row sums (reduce over the 8 strips in this row)
    #pragma unroll
    for (int l = 0; l < 5; l++) {
        float v = lvl[l];
        v += __shfl_xor_sync(0xffffffffu, v, 1);
        v += __shfl_xor_sync(0xffffffffu, v, 2);
        v += __shfl_xor_sync(0xffffffffu, v, 4);
        if (s8 == 0) sred[l][py] = v;
    }
    // level 5 + stats: 16-px half-row sums (4-strip groups)
    {
        float v5 = lvl[5], vs = s_stat, vq = q_stat;
        v5 += __shfl_xor_sync(0xffffffffu, v5, 1);
        v5 += __shfl_xor_sync(0xffffffffu, v5, 2);
        vs += __shfl_xor_sync(0xffffffffu, vs, 1);
        vs += __shfl_xor_sync(0xffffffffu, vs, 2);
        vq += __shfl_xor_sync(0xffffffffu, vq, 1);
        vq += __shfl_xor_sync(0xffffffffu, vq, 2);
        if ((s8 & 3) == 0) {
            int h = s8 >> 2;
            s5[py][h] = v5;
            sh_s[py][h] = vs;
            sh_q[py][h] = vq;
        }
    }
    __syncthreads();

    float* eb = g_edge + (size_t)b * NODES;
    if (t < 160) {                     // warps 0..4 finish levels 0..4
        int l = t >> 5, lane = t & 31;
        float w = sred[l][lane];
        #pragma unroll
        for (int o = 16; o; o >>= 1) w += __shfl_xor_sync(0xffffffffu, w, o);
        if (lane == 0) {
            if (l == 4) eb[85 + ty * 16 + tx] = w;
            else        g_epart[(b * 4 + l) * 256 + ty * 16 + tx] = w;
        }
    }
    if (t >= 160 && t < 164) {         // level-5 edge quadrants
        int q = t - 160, qy = q >> 1, qx = q & 1;
        float w = 0.0f;
        #pragma unroll
        for (int r = 0; r < 16; r++) w += s5[qy * 16 + r][qx];
        eb[341 + (ty * 2 + qy) * 32 + (tx * 2 + qx)] = w;
    }
    if (t >= 192 && t < 196) {         // stats quadrants
        int q = t - 192, qy = q >> 1, qx = q & 1;
        float as = 0.0f, aq = 0.0f;
        #pragma unroll
        for (int r = 0; r < 16; r++) {
            as += sh_s[qy * 16 + r][qx];
            aq += sh_q[qy * 16 + r][qx];
        }
        int leaf = (ty * 2 + qy) * 32 + (tx * 2 + qx);
        g_sum[b * NODES + 341 + leaf] = as;
        g_ssq[b * NODES + 341 + leaf] = aq;
    }
}

// ============================================================
// K2: per-batch tree aggregation + DFS decode table build.
// ============================================================
__global__ void k_aggregate() {
    int b = blockIdx.x;
    int t = threadIdx.x;  // 256
    __shared__ float sp[256];

    // ---- DFS decode table (batch-independent; 8192 threads cover 5461)
    {
        int p = b * 256 + t;
        if (p < NODES_ALL) {
            int level = 0, row = 0, col = 0, pp = p, plen = 0;
            unsigned pathbits = 0;
            #pragma unroll
            for (int L = 0; L < 6; L++) {
                if (pp > 0) {
                    pp--;
                    const int s = ((1 << (2 * (6 - L))) - 1) / 3;  // 1365,341,85,21,5,1
                    int ci = pp / s;
                    pp -= ci * s;
                    int q = (0x3102 >> (ci * 4)) & 0xF;            // HILBERT=[2,0,1,3]
                    row = 2 * row + (q >> 1);
                    col = 2 * col + (q & 1);
                    pathbits |= (unsigned)q << (3 * plen);
                    plen++;
                    level++;
                }
            }
            int node = c_off[level] + (row << level) + col;
            uint2 w;
            w.x = (unsigned)node | ((unsigned)level << 16) |
                  ((unsigned)row << 19) | ((unsigned)col << 25);
            w.y = pathbits | ((unsigned)plen << 24);
            g_tbl[p] = w;
        }
    }

    // edge levels 0..3 from per-tile partials
    #pragma unroll
    for (int l = 0; l < 4; l++) {
        sp[t] = g_epart[(b * 4 + l) * 256 + t];
        __syncthreads();
        int n = 1 << l, P = 16 >> l;
        if (t < n * n) {
            int r = t >> l, c = t & (n - 1);
            float acc = 0.0f;
            for (int dy = 0; dy < P; dy++)
                for (int dx = 0; dx < P; dx++)
                    acc += sp[(r * P + dy) * 16 + (c * P + dx)];
            g_edge[(size_t)b * NODES + c_off[l] + t] = acc;
        }
        __syncthreads();
    }

    // sum/ssq quadtree aggregation, levels 4..0
    float* S = g_sum + (size_t)b * NODES;
    float* Q = g_ssq + (size_t)b * NODES;
    for (int l = 4; l >= 0; l--) {
        int n = 1 << l, nn = n << 1;
        int cb = c_off[l + 1], ob = c_off[l];
        for (int i = t; i < n * n; i += blockDim.x) {
            int r = i >> l, c = i & (n - 1);
            int k0 = cb + (2 * r) * nn + 2 * c;
            int k2 = k0 + nn;
            S[ob + i] = S[k0] + S[k0 + 1] + S[k2] + S[k2 + 1];
            Q[ob + i] = Q[k0] + Q[k0 + 1] + Q[k2] + Q[k2 + 1];
        }
        __syncthreads();
    }
}

// ============================================================
// K3: tiled MLP. 64 items per CTA (107KB smem -> 2 CTAs/SM).
// split = (logit >= 0)  (sigmoid(x)>=0.5 <=> x>=0)
// ============================================================
#define MLP_ITEMS 64
#define MLP_SMEM_FLOATS 26752   // 107,008 bytes

__global__ void k_mlp(const float* __restrict__ W1, const float* __restrict__ b1,
                      const float* __restrict__ W2, const float* __restrict__ b2,
                      const float* __restrict__ W3, const float* __restrict__ b3,
                      const float* __restrict__ W4, const float* __restrict__ b4) {
    extern __shared__ float sm[];
    float* sW1 = sm;                 // 768
    float* sb1 = sW1 + 768;          // 128
    float* sW2 = sb1 + 128;          // 8192
    float* sb2 = sW2 + 8192;         // 64
    float* sW3 = sb2 + 64;           // 2048
    float* sb3 = sW3 + 2048;         // 32
    float* sW4 = sb3 + 32;           // 32
    float* sF  = sW4 + 32;           // 6*64
    float* sH1 = sF + 384;           // 64*132
    float* sH2 = sH1 + 64 * 132;     // 64*68
    float* sH3 = sH2 + 64 * 68;      // 64*36

    int t = threadIdx.x;  // 256
    for (int i = t; i < 768; i += 256) sW1[i] = W1[i];
    for (int i = t; i < 128; i += 256) sb1[i] = b1[i];
    for (int i = t; i < 8192; i += 256) sW2[i] = W2[i];
    if (t < 64) sb2[t] = b2[t];
    for (int i = t; i < 2048; i += 256) sW3[i] = W3[i];
    if (t < 32) { sb3[t] = b3[t]; sW4[t] = W4[t]; }
    float bias4 = b4[0];
    int base = blockIdx.x * MLP_ITEMS;

    // phase 1: features
    if (t < MLP_ITEMS) {
        int item = base + t;
        float f0 = 0, f1 = 0, fv = 0, fm = 0, fe = 0;
        if (item < BATCH * NODES) {
            int node = item % NODES;
            int l = node < 1 ? 0 : node < 5 ? 1 : node < 21 ? 2 : node < 85 ? 3 : node < 341 ? 4 : 5;
            int hl = 512 >> l;
            float N = 3.0f * (float)hl * (float)hl;
            float s = g_sum[item], q = g_ssq[item], e = g_edge[item];
            float mean = s / N;
            float var = (q - s * mean) / (N - 1.0f);
            float edge = e / ((float)hl * (float)hl);
            f0 = (float)l; f1 = (float)hl; fv = var; fm = mean; fe = edge;
        }
        sF[0 * 64 + t] = f0;
        sF[1 * 64 + t] = f1;
        sF[2 * 64 + t] = f1;
        sF[3 * 64 + t] = fv;
        sF[4 * 64 + t] = fm;
        sF[5 * 64 + t] = fe;
    }
    __syncthreads();

    // phase 2: H1 = relu(F @ W1 + b1)
    {
        int it = t >> 2;
        int j0 = (t & 3) * 32;
        float f[6];
        #pragma unroll
        for (int i = 0; i < 6; i++) f[i] = sF[i * 64 + it];
        for (int j = j0; j < j0 + 32; j++) {
            float acc = sb1[j];
            #pragma unroll
            for (int i = 0; i < 6; i++) acc += f[i] * sW1[i * 128 + j];
            sH1[it * 132 + j] = fmaxf(acc, 0.0f);
        }
    }
    __syncthreads();

    // phase 3: H2 = relu(H1 @ W2 + b2)
    {
        int it0 = (t >> 3) * 2;
        int j0 = (t & 7) * 8;
        float acc[2][8];
        #pragma unroll
        for (int m = 0; m < 2; m++)
            #pragma unroll
            for (int j = 0; j < 8; j++) acc[m][j] = sb2[j0 + j];
        for (int i = 0; i < 128; i += 4) {
            float a[2][4];
            #pragma unroll
            for (int m = 0; m < 2; m++) {
                float4 v = *(const float4*)&sH1[(it0 + m) * 132 + i];
                a[m][0] = v.x; a[m][1] = v.y; a[m][2] = v.z; a[m][3] = v.w;
            }
            #pragma unroll
            for (int k = 0; k < 4; k++) {
                float4 w0 = *(const float4*)&sW2[(i + k) * 64 + j0];
                float4 w1 = *(const float4*)&sW2[(i + k) * 64 + j0 + 4];
                float wv[8] = {w0.x, w0.y, w0.z, w0.w, w1.x, w1.y, w1.z, w1.w};
                #pragma unroll
                for (int m = 0; m < 2; m++)
                    #pragma unroll
                    for (int j = 0; j < 8; j++) acc[m][j] += a[m][k] * wv[j];
            }
        }
        #pragma unroll
        for (int m = 0; m < 2; m++)
            #pragma unroll
            for (int j = 0; j < 8; j++)
                sH2[(it0 + m) * 68 + j0 + j] = fmaxf(acc[m][j], 0.0f);
    }
    __syncthreads();

    // phase 4: H3 = relu(H2 @ W3 + b3)
    {
        int it = t >> 2;
        int j0 = (t & 3) * 8;
        float acc[8];
        #pragma unroll
        for (int j = 0; j < 8; j++) acc[j] = sb3[j0 + j];
        for (int i = 0; i < 64; i += 4) {
            float4 v = *(const float4*)&sH2[it * 68 + i];
            float a[4] = {v.x, v.y, v.z, v.w};
            #pragma unroll
            for (int k = 0; k < 4; k++) {
                float4 w0 = *(const float4*)&sW3[(i + k) * 32 + j0];
                float4 w1 = *(const float4*)&sW3[(i + k) * 32 + j0 + 4];
                float wv[8] = {w0.x, w0.y, w0.z, w0.w, w1.x, w1.y, w1.z, w1.w};
                #pragma unroll
                for (int j = 0; j < 8; j++) acc[j] += a[k] * wv[j];
            }
        }
        #pragma unroll
        for (int j = 0; j < 8; j++)
            sH3[it * 36 + j0 + j] = fmaxf(acc[j], 0.0f);
    }
    __syncthreads();

    // phase 5: logit sign
    if (t < MLP_ITEMS) {
        int item = base + t;
        float acc = bias4;
        #pragma unroll
        for (int k = 0; k < 32; k += 4) {
            float4 h = *(const float4*)&sH3[t * 36 + k];
            float4 w = *(const float4*)&sW4[k];
            acc += h.x * w.x + h.y * w.y + h.z * w.z + h.w * w.w;
        }
        if (item < BATCH * NODES) g_split[item] = (unsigned char)(acc >= 0.0f);
    }
}

// ============================================================
// K3b: per-(b,dfs) mask from ancestor split chain. One thread each.
// ============================================================
__global__ void __launch_bounds__(256) k_maskcalc() {
    int i = blockIdx.x * 256 + threadIdx.x;
    if (i >= BATCH * NODES_ALL) return;
    int b = i / NODES_ALL;
    int p = i - b * NODES_ALL;
    uint2 w = g_tbl[p];
    int node  = w.x & 0xFFFF;
    int level = (w.x >> 16) & 7;
    int row   = (w.x >> 19) & 63;
    int col   = (w.x >> 25) & 63;
    const unsigned char* sp = g_split + (size_t)b * NODES;
    bool alive = true;
    #pragma unroll
    for (int j = 0; j < 6; j++) {
        if (j < level) {
            int idx = c_off[j] + ((row >> (level - j)) << j) + (col >> (level - j));
            alive = alive && (sp[idx] != 0);
        }
    }
    float m;
    if (level < 6) m = (alive && sp[node] == 0) ? 1.0f : 0.0f;
    else           m = alive ? 1.0f : 0.0f;
    g_maskf[i] = m;
}

// ============================================================
// K4: thread-per-float4 token writer (coalesced streaming stores).
// ============================================================
__global__ void __launch_bounds__(256) k_write(const float* __restrict__ img,
                                               float* __restrict__ out) {
    long long idx = (long long)blockIdx.x * 256 + threadIdx.x;   // < B*NODES_ALL*48
    int gw = (int)(idx / 48);
    int f4 = (int)(idx - (long long)gw * 48);
    if (gw >= BATCH * NODES_ALL) return;
    int b = gw / NODES_ALL;
    int p = gw - b * NODES_ALL;

    uint2 w = g_tbl[p];
    int level = (w.x >> 16) & 7;
    int row   = (w.x >> 19) & 63;
    int col   = (w.x >> 25) & 63;
    float m = g_maskf[gw];

    // f4 -> (channel, patch row, half): token layout c*64 + r*8 + h*4
    int c = f4 >> 4, r = (f4 >> 1) & 7, h = f4 & 1;

    float4 v = make_float4(0.0f, 0.0f, 0.0f, 0.0f);
    if (m != 0.0f) {
        int hl = 512 >> level;
        int Y0 = row * hl + ((hl - 8) >> 1);
        int X0 = col * hl + ((hl - 8) >> 1);
        const float* src = img + ((size_t)(b * 3 + c) * 512 + (size_t)(Y0 + r)) * 512
                               + X0 + h * 4;
        v = __ldg((const float4*)src);
    }
    st_cs_f4(out + (size_t)gw * 192 + f4 * 4, v);

    if (f4 == 0) {
        out[MASK_OFF_ + (size_t)gw] = m;
        if (b == 0) {
            unsigned pathbits = w.y & 0xFFFFFF;
            int plen = (int)(w.y >> 24);
            float* ip = out + INFO_OFF_ + (size_t)p * 16;
            ip[0] = (float)level;
            #pragma unroll
            for (int k = 1; k < 16; k++)
                ip[k] = (k - 1 < plen) ? (float)((pathbits >> (3 * (k - 1))) & 7) : 0.0f;
        }
    }
}

// ============================================================
extern "C" void kernel_launch(void* const* d_in, const int* in_sizes, int n_in,
                              void* d_out, int out_size) {
    const float* img = (const float*)d_in[0];
    const float* W1 = (const float*)d_in[1];
    const float* b1 = (const float*)d_in[2];
    const float* W2 = (const float*)d_in[3];
    const float* b2 = (const float*)d_in[4];
    const float* W3 = (const float*)d_in[5];
    const float* b3 = (const float*)d_in[6];
    const float* W4 = (const float*)d_in[7];
    const float* b4 = (const float*)d_in[8];
    float* out = (float*)d_out;

    cudaFuncSetAttribute(k_mlp, cudaFuncAttributeMaxDynamicSharedMemorySize,
                         MLP_SMEM_FLOATS * (int)sizeof(float));

    k_gray_edge<<<dim3(256, BATCH), 256>>>(img);
    k_aggregate<<<BATCH, 256>>>();
    int mlp_blocks = (BATCH * NODES + MLP_ITEMS - 1) / MLP_ITEMS;  // 683
    k_mlp<<<mlp_blocks, 256, MLP_SMEM_FLOATS * sizeof(float)>>>(W1, b1, W2, b2, W3, b3, W4, b4);
    k_maskcalc<<<(BATCH * NODES_ALL + 255) / 256, 256>>>();
    long long nthreads = (long long)BATCH * NODES_ALL * 48;
    k_write<<<(unsigned)((nthreads + 255) / 256), 256>>>(img, out);
}

// round 10
// speedup vs baseline: 1.5360x; 1.0001x over previous
#include <cuda_runtime.h>
#include <cstdint>

#define BATCH 32
#define NODES 1365         // nodes levels 0..5
#define NODES_ALL 5461     // nodes levels 0..6

static const long long TOK_ELEMS = (long long)BATCH * NODES_ALL * 192; // 33,552,384
static const long long MASK_OFF_ = TOK_ELEMS;
static const long long INFO_OFF_ = TOK_ELEMS + (long long)BATCH * NODES_ALL;

__device__ __constant__ int c_off[8] = {0, 1, 5, 21, 85, 341, 1365, 5461};

// ---- scratch (device globals; no allocations allowed) ----
__device__ float g_sum[BATCH * NODES];
__device__ float g_ssq[BATCH * NODES];
__device__ float g_edge[BATCH * NODES];
__device__ float g_epart[BATCH * 4 * 256];           // per-tile partial edge sums, levels 0..3
__device__ unsigned char g_split[BATCH * NODES];
__device__ uint2 g_tbl[NODES_ALL];                   // DFS decode table
__device__ float g_maskf[BATCH * NODES_ALL];         // per-(b,dfs) mask

__device__ __forceinline__ float fast_sqrt(float x) {
    float r;
    asm("sqrt.approx.f32 %0, %1;" : "=f"(r) : "f"(x));
    return r;
}

__device__ __forceinline__ void st_cs_f4(float* p, float4 v) {
    asm volatile("st.global.cs.v4.f32 [%0], {%1,%2,%3,%4};"
                 :: "l"(p), "f"(v.x), "f"(v.y), "f"(v.z), "f"(v.w) : "memory");
}

// ============================================================
// K1: fused gray + level-5 stats + per-level Sobel edge sums.
// One CTA = one 32x32 pixel tile, 256 threads, 4 pixels/thread.
// ============================================================
__global__ void __launch_bounds__(256) k_gray_edge(const float* __restrict__ img) {
    int b = blockIdx.y;
    int ty = blockIdx.x >> 4, tx = blockIdx.x & 15;
    __shared__ float sg[34][36];
    __shared__ float sred[5][32];
    __shared__ float s5[32][2];
    __shared__ float sh_s[32][2], sh_q[32][2];
    int t = threadIdx.x;               // 256
    int py = t >> 3, s8 = t & 7;       // row 0..31, strip 0..7
    int px0 = s8 * 4;
    int Y = ty * 32 + py;
    int X0 = tx * 32 + px0;

    const float* ib = img + (size_t)b * 3 * 262144;
    size_t pidx = (size_t)Y * 512 + X0;
    float4 v0 = *(const float4*)(ib + pidx);
    float4 v1 = *(const float4*)(ib + pidx + 262144);
    float4 v2 = *(const float4*)(ib + pidx + 524288);
    float gr0 = (v0.x + v1.x + v2.x) * (1.0f / 3.0f);
    float gr1 = (v0.y + v1.y + v2.y) * (1.0f / 3.0f);
    float gr2 = (v0.z + v1.z + v2.z) * (1.0f / 3.0f);
    float gr3 = (v0.w + v1.w + v2.w) * (1.0f / 3.0f);
    float s_stat = (v0.x + v1.x + v2.x) + (v0.y + v1.y + v2.y)
                 + (v0.z + v1.z + v2.z) + (v0.w + v1.w + v2.w);
    float q_stat = v0.x * v0.x + v0.y * v0.y + v0.z * v0.z + v0.w * v0.w
                 + v1.x * v1.x + v1.y * v1.y + v1.z * v1.z + v1.w * v1.w
                 + v2.x * v2.x + v2.y * v2.y + v2.z * v2.z + v2.w * v2.w;
    sg[py + 1][px0 + 1] = gr0;
    sg[py + 1][px0 + 2] = gr1;
    sg[py + 1][px0 + 3] = gr2;
    sg[py + 1][px0 + 4] = gr3;

    // halo: 132 perimeter pixels of the 34x34 window
    if (t < 132) {
        int sy, sx;
        if (t < 34)       { sy = 0;           sx = t; }
        else if (t < 68)  { sy = 33;          sx = t - 34; }
        else if (t < 100) { sy = t - 68 + 1;  sx = 0; }
        else              { sy = t - 100 + 1; sx = 33; }
        int gy = ty * 32 - 1 + sy, gx = tx * 32 - 1 + sx;
        float v = 0.0f;
        if (gy >= 0 && gy < 512 && gx >= 0 && gx < 512) {
            size_t q = (size_t)gy * 512 + gx;
            v = (ib[q] + ib[q + 262144] + ib[q + 524288]) * (1.0f / 3.0f);
        }
        sg[sy][sx] = v;
    }
    __syncthreads();

    // 3x6 window covering the 4-pixel strip (+1 halo each side)
    float g[3][6];
    #pragma unroll
    for (int r = 0; r < 3; r++)
        #pragma unroll
        for (int c = 0; c < 6; c++)
            g[r][c] = sg[py + r][px0 + c];

    float lvl[6] = {0, 0, 0, 0, 0, 0};
    #pragma unroll
    for (int i = 0; i < 4; i++) {
        int xg = X0 + i;
        float Et = g[0][i + 2], Em2 = 2.0f * g[1][i + 2], Eb = g[2][i + 2];
        float Wt = g[0][i],     Wm2 = 2.0f * g[1][i],     Wb = g[2][i];
        float Nl = g[0][i], Nm2 = 2.0f * g[0][i + 1], Nr = g[0][i + 2];
        float Sl = g[2][i], Sm2 = 2.0f * g[2][i + 1], Sr = g[2][i + 2];
        float E_nt = Em2 + Eb, E_nb = Et + Em2, E_f = E_nt + Et;
        float W_nt = Wm2 + Wb, W_nb = Wt + Wm2, W_f = W_nt + Wt;
        float N_nl = Nm2 + Nr, N_nr = Nl + Nm2, N_f = N_nl + Nl;
        float S_nl = Sm2 + Sr, S_nr = Sl + Sm2, S_f = S_nl + Sl;
        #pragma unroll
        for (int l = 0; l < 6; l++) {
            int hm = (512 >> l) - 1;
            bool bt = (Y  & hm) == 0, bb = (Y  & hm) == hm;
            bool bl = (xg & hm) == 0, br = (xg & hm) == hm;
            float Ec = bt ? E_nt : (bb ? E_nb : E_f);
            float Wc = bt ? W_nt : (bb ? W_nb : W_f);
            float ex = (br ? 0.0f : Ec) - (bl ? 0.0f : Wc);
            float Nc = bl ? N_nl : (br ? N_nr : N_f);
            float Sc = bl ? S_nl : (br ? S_nr : S_f);
            float ey = (bb ? 0.0f : Sc) - (bt ? 0.0f : Nc);
            lvl[l] += fast_sqrt(ex * ex + ey * ey);
        }
    }

    // levels 0..4: 32-px row sums (reduce over the 8 strips in this row)
    #pragma unroll
    for (int l = 0; l < 5; l++) {
        float v = lvl[l];
        v += __shfl_xor_sync(0xffffffffu, v, 1);
        v += __shfl_xor_sync(0xffffffffu, v, 2);
        v += __shfl_xor_sync(0xffffffffu, v, 4);
        if (s8 == 0) sred[l][py] = v;
    }
    // level 5 + stats: 16-px half-row sums (4-strip groups)
    {
        float v5 = lvl[5], vs = s_stat, vq = q_stat;
        v5 += __shfl_xor_sync(0xffffffffu, v5, 1);
        v5 += __shfl_xor_sync(0xffffffffu, v5, 2);
        vs += __shfl_xor_sync(0xffffffffu, vs, 1);
        vs += __shfl_xor_sync(0xffffffffu, vs, 2);
        vq += __shfl_xor_sync(0xffffffffu, vq, 1);
        vq += __shfl_xor_sync(0xffffffffu, vq, 2);
        if ((s8 & 3) == 0) {
            int h = s8 >> 2;
            s5[py][h] = v5;
            sh_s[py][h] = vs;
            sh_q[py][h] = vq;
        }
    }
    __syncthreads();

    float* eb = g_edge + (size_t)b * NODES;
    if (t < 160) {                     // warps 0..4 finish levels 0..4
        int l = t >> 5, lane = t & 31;
        float w = sred[l][lane];
        #pragma unroll
        for (int o = 16; o; o >>= 1) w += __shfl_xor_sync(0xffffffffu, w, o);
        if (lane == 0) {
            if (l == 4) eb[85 + ty * 16 + tx] = w;
            else        g_epart[(b * 4 + l) * 256 + ty * 16 + tx] = w;
        }
    }
    if (t >= 160 && t < 164) {         // level-5 edge quadrants
        int q = t - 160, qy = q >> 1, qx = q & 1;
        float w = 0.0f;
        #pragma unroll
        for (int r = 0; r < 16; r++) w += s5[qy * 16 + r][qx];
        eb[341 + (ty * 2 + qy) * 32 + (tx * 2 + qx)] = w;
    }
    if (t >= 192 && t < 196) {         // stats quadrants
        int q = t - 192, qy = q >> 1, qx = q & 1;
        float as = 0.0f, aq = 0.0f;
        #pragma unroll
        for (int r = 0; r < 16; r++) {
            as += sh_s[qy * 16 + r][qx];
            aq += sh_q[qy * 16 + r][qx];
        }
        int leaf = (ty * 2 + qy) * 32 + (tx * 2 + qx);
        g_sum[b * NODES + 341 + leaf] = as;
        g_ssq[b * NODES + 341 + leaf] = aq;
    }
}

// ============================================================
// K2: per-batch tree aggregation + DFS decode table build.
// ============================================================
__global__ void k_aggregate() {
    int b = blockIdx.x;
    int t = threadIdx.x;  // 256
    __shared__ float sp[256];

    // ---- DFS decode table (batch-independent; 8192 threads cover 5461)
    {
        int p = b * 256 + t;
        if (p < NODES_ALL) {
            int level = 0, row = 0, col = 0, pp = p, plen = 0;
            unsigned pathbits = 0;
            #pragma unroll
            for (int L = 0; L < 6; L++) {
                if (pp > 0) {
                    pp--;
                    const int s = ((1 << (2 * (6 - L))) - 1) / 3;  // 1365,341,85,21,5,1
                    int ci = pp / s;
                    pp -= ci * s;
                    int q = (0x3102 >> (ci * 4)) & 0xF;            // HILBERT=[2,0,1,3]
                    row = 2 * row + (q >> 1);
                    col = 2 * col + (q & 1);
                    pathbits |= (unsigned)q << (3 * plen);
                    plen++;
                    level++;
                }
            }
            int node = c_off[level] + (row << level) + col;
            uint2 w;
            w.x = (unsigned)node | ((unsigned)level << 16) |
                  ((unsigned)row << 19) | ((unsigned)col << 25);
            w.y = pathbits | ((unsigned)plen << 24);
            g_tbl[p] = w;
        }
    }

    // edge levels 0..3 from per-tile partials
    #pragma unroll
    for (int l = 0; l < 4; l++) {
        sp[t] = g_epart[(b * 4 + l) * 256 + t];
        __syncthreads();
        int n = 1 << l, P = 16 >> l;
        if (t < n * n) {
            int r = t >> l, c = t & (n - 1);
            float acc = 0.0f;
            for (int dy = 0; dy < P; dy++)
                for (int dx = 0; dx < P; dx++)
                    acc += sp[(r * P + dy) * 16 + (c * P + dx)];
            g_edge[(size_t)b * NODES + c_off[l] + t] = acc;
        }
        __syncthreads();
    }

    // sum/ssq quadtree aggregation, levels 4..0
    float* S = g_sum + (size_t)b * NODES;
    float* Q = g_ssq + (size_t)b * NODES;
    for (int l = 4; l >= 0; l--) {
        int n = 1 << l, nn = n << 1;
        int cb = c_off[l + 1], ob = c_off[l];
        for (int i = t; i < n * n; i += blockDim.x) {
            int r = i >> l, c = i & (n - 1);
            int k0 = cb + (2 * r) * nn + 2 * c;
            int k2 = k0 + nn;
            S[ob + i] = S[k0] + S[k0 + 1] + S[k2] + S[k2 + 1];
            Q[ob + i] = Q[k0] + Q[k0 + 1] + Q[k2] + Q[k2 + 1];
        }
        __syncthreads();
    }
}

// ============================================================
// K3: tiled MLP. 64 items per CTA (107KB smem -> 2 CTAs/SM).
// split = (logit >= 0)  (sigmoid(x)>=0.5 <=> x>=0)
// ============================================================
#define MLP_ITEMS 64
#define MLP_SMEM_FLOATS 26752   // 107,008 bytes

__global__ void k_mlp(const float* __restrict__ W1, const float* __restrict__ b1,
                      const float* __restrict__ W2, const float* __restrict__ b2,
                      const float* __restrict__ W3, const float* __restrict__ b3,
                      const float* __restrict__ W4, const float* __restrict__ b4) {
    extern __shared__ float sm[];
    float* sW1 = sm;                 // 768
    float* sb1 = sW1 + 768;          // 128
    float* sW2 = sb1 + 128;          // 8192
    float* sb2 = sW2 + 8192;         // 64
    float* sW3 = sb2 + 64;           // 2048
    float* sb3 = sW3 + 2048;         // 32
    float* sW4 = sb3 + 32;           // 32
    float* sF  = sW4 + 32;           // 6*64
    float* sH1 = sF + 384;           // 64*132
    float* sH2 = sH1 + 64 * 132;     // 64*68
    float* sH3 = sH2 + 64 * 68;      // 64*36

    int t = threadIdx.x;  // 256
    for (int i = t; i < 768; i += 256) sW1[i] = W1[i];
    for (int i = t; i < 128; i += 256) sb1[i] = b1[i];
    for (int i = t; i < 8192; i += 256) sW2[i] = W2[i];
    if (t < 64) sb2[t] = b2[t];
    for (int i = t; i < 2048; i += 256) sW3[i] = W3[i];
    if (t < 32) { sb3[t] = b3[t]; sW4[t] = W4[t]; }
    float bias4 = b4[0];
    int base = blockIdx.x * MLP_ITEMS;

    // phase 1: features
    if (t < MLP_ITEMS) {
        int item = base + t;
        float f0 = 0, f1 = 0, fv = 0, fm = 0, fe = 0;
        if (item < BATCH * NODES) {
            int node = item % NODES;
            int l = node < 1 ? 0 : node < 5 ? 1 : node < 21 ? 2 : node < 85 ? 3 : node < 341 ? 4 : 5;
            int hl = 512 >> l;
            float N = 3.0f * (float)hl * (float)hl;
            float s = g_sum[item], q = g_ssq[item], e = g_edge[item];
            float mean = s / N;
            float var = (q - s * mean) / (N - 1.0f);
            float edge = e / ((float)hl * (float)hl);
            f0 = (float)l; f1 = (float)hl; fv = var; fm = mean; fe = edge;
        }
        sF[0 * 64 + t] = f0;
        sF[1 * 64 + t] = f1;
        sF[2 * 64 + t] = f1;
        sF[3 * 64 + t] = fv;
        sF[4 * 64 + t] = fm;
        sF[5 * 64 + t] = fe;
    }
    __syncthreads();

    // phase 2: H1 = relu(F @ W1 + b1)
    {
        int it = t >> 2;
        int j0 = (t & 3) * 32;
        float f[6];
        #pragma unroll
        for (int i = 0; i < 6; i++) f[i] = sF[i * 64 + it];
        for (int j = j0; j < j0 + 32; j++) {
            float acc = sb1[j];
            #pragma unroll
            for (int i = 0; i < 6; i++) acc += f[i] * sW1[i * 128 + j];
            sH1[it * 132 + j] = fmaxf(acc, 0.0f);
        }
    }
    __syncthreads();

    // phase 3: H2 = relu(H1 @ W2 + b2)
    {
        int it0 = (t >> 3) * 2;
        int j0 = (t & 7) * 8;
        float acc[2][8];
        #pragma unroll
        for (int m = 0; m < 2; m++)
            #pragma unroll
            for (int j = 0; j < 8; j++) acc[m][j] = sb2[j0 + j];
        for (int i = 0; i < 128; i += 4) {
            float a[2][4];
            #pragma unroll
            for (int m = 0; m < 2; m++) {
                float4 v = *(const float4*)&sH1[(it0 + m) * 132 + i];
                a[m][0] = v.x; a[m][1] = v.y; a[m][2] = v.z; a[m][3] = v.w;
            }
            #pragma unroll
            for (int k = 0; k < 4; k++) {
                float4 w0 = *(const float4*)&sW2[(i + k) * 64 + j0];
                float4 w1 = *(const float4*)&sW2[(i + k) * 64 + j0 + 4];
                float wv[8] = {w0.x, w0.y, w0.z, w0.w, w1.x, w1.y, w1.z, w1.w};
                #pragma unroll
                for (int m = 0; m < 2; m++)
                    #pragma unroll
                    for (int j = 0; j < 8; j++) acc[m][j] += a[m][k] * wv[j];
            }
        }
        #pragma unroll
        for (int m = 0; m < 2; m++)
            #pragma unroll
            for (int j = 0; j < 8; j++)
                sH2[(it0 + m) * 68 + j0 + j] = fmaxf(acc[m][j], 0.0f);
    }
    __syncthreads();

    // phase 4: H3 = relu(H2 @ W3 + b3)
    {
        int it = t >> 2;
        int j0 = (t & 3) * 8;
        float acc[8];
        #pragma unroll
        for (int j = 0; j < 8; j++) acc[j] = sb3[j0 + j];
        for (int i = 0; i < 64; i += 4) {
            float4 v = *(const float4*)&sH2[it * 68 + i];
            float a[4] = {v.x, v.y, v.z, v.w};
            #pragma unroll
            for (int k = 0; k < 4; k++) {
                float4 w0 = *(const float4*)&sW3[(i + k) * 32 + j0];
                float4 w1 = *(const float4*)&sW3[(i + k) * 32 + j0 + 4];
                float wv[8] = {w0.x, w0.y, w0.z, w0.w, w1.x, w1.y, w1.z, w1.w};
                #pragma unroll
                for (int j = 0; j < 8; j++) acc[j] += a[k] * wv[j];
            }
        }
        #pragma unroll
        for (int j = 0; j < 8; j++)
            sH3[it * 36 + j0 + j] = fmaxf(acc[j], 0.0f);
    }
    __syncthreads();

    // phase 5: logit sign
    if (t < MLP_ITEMS) {
        int item = base + t;
        float acc = bias4;
        #pragma unroll
        for (int k = 0; k < 32; k += 4) {
            float4 h = *(const float4*)&sH3[t * 36 + k];
            float4 w = *(const float4*)&sW4[k];
            acc += h.x * w.x + h.y * w.y + h.z * w.z + h.w * w.w;
        }
        if (item < BATCH * NODES) g_split[item] = (unsigned char)(acc >= 0.0f);
    }
}

// ============================================================
// K3b: per-(b,dfs) mask from ancestor split chain. One thread each.
// ============================================================
__global__ void __launch_bounds__(256) k_maskcalc() {
    int i = blockIdx.x * 256 + threadIdx.x;
    if (i >= BATCH * NODES_ALL) return;
    int b = i / NODES_ALL;
    int p = i - b * NODES_ALL;
    uint2 w = g_tbl[p];
    int node  = w.x & 0xFFFF;
    int level = (w.x >> 16) & 7;
    int row   = (w.x >> 19) & 63;
    int col   = (w.x >> 25) & 63;
    const unsigned char* sp = g_split + (size_t)b * NODES;
    bool alive = true;
    #pragma unroll
    for (int j = 0; j < 6; j++) {
        if (j < level) {
            int idx = c_off[j] + ((row >> (level - j)) << j) + (col >> (level - j));
            alive = alive && (sp[idx] != 0);
        }
    }
    float m;
    if (level < 6) m = (alive && sp[node] == 0) ? 1.0f : 0.0f;
    else           m = alive ? 1.0f : 0.0f;
    g_maskf[i] = m;
}

// ============================================================
// K4: thread-per-float4 token writer (coalesced streaming stores).
// ============================================================
__global__ void __launch_bounds__(256) k_write(const float* __restrict__ img,
                                               float* __restrict__ out) {
    long long idx = (long long)blockIdx.x * 256 + threadIdx.x;   // < B*NODES_ALL*48
    int gw = (int)(idx / 48);
    int f4 = (int)(idx - (long long)gw * 48);
    if (gw >= BATCH * NODES_ALL) return;
    int b = gw / NODES_ALL;
    int p = gw - b * NODES_ALL;

    uint2 w = g_tbl[p];
    int level = (w.x >> 16) & 7;
    int row   = (w.x >> 19) & 63;
    int col   = (w.x >> 25) & 63;
    float m = g_maskf[gw];

    // f4 -> (channel, patch row, half): token layout c*64 + r*8 + h*4
    int c = f4 >> 4, r = (f4 >> 1) & 7, h = f4 & 1;

    float4 v = make_float4(0.0f, 0.0f, 0.0f, 0.0f);
    if (m != 0.0f) {
        int hl = 512 >> level;
        int Y0 = row * hl + ((hl - 8) >> 1);
        int X0 = col * hl + ((hl - 8) >> 1);
        const float* src = img + ((size_t)(b * 3 + c) * 512 + (size_t)(Y0 + r)) * 512
                               + X0 + h * 4;
        v = __ldg((const float4*)src);
    }
    st_cs_f4(out + (size_t)gw * 192 + f4 * 4, v);

    if (f4 == 0) {
        out[MASK_OFF_ + (size_t)gw] = m;
        if (b == 0) {
            unsigned pathbits = w.y & 0xFFFFFF;
            int plen = (int)(w.y >> 24);
            float* ip = out + INFO_OFF_ + (size_t)p * 16;
            ip[0] = (float)level;
            #pragma unroll
            for (int k = 1; k < 16; k++)
                ip[k] = (k - 1 < plen) ? (float)((pathbits >> (3 * (k - 1))) & 7) : 0.0f;
        }
    }
}

// ============================================================
extern "C" void kernel_launch(void* const* d_in, const int* in_sizes, int n_in,
                              void* d_out, int out_size) {
    const float* img = (const float*)d_in[0];
    const float* W1 = (const float*)d_in[1];
    const float* b1 = (const float*)d_in[2];
    const float* W2 = (const float*)d_in[3];
    const float* b2 = (const float*)d_in[4];
    const float* W3 = (const float*)d_in[5];
    const float* b3 = (const float*)d_in[6];
    const float* W4 = (const float*)d_in[7];
    const float* b4 = (const float*)d_in[8];
    float* out = (float*)d_out;

    cudaFuncSetAttribute(k_mlp, cudaFuncAttributeMaxDynamicSharedMemorySize,
                         MLP_SMEM_FLOATS * (int)sizeof(float));

    k_gray_edge<<<dim3(256, BATCH), 256>>>(img);
    k_aggregate<<<BATCH, 256>>>();
    int mlp_blocks = (BATCH * NODES + MLP_ITEMS - 1) / MLP_ITEMS;  // 683
    k_mlp<<<mlp_blocks, 256, MLP_SMEM_FLOATS * sizeof(float)>>>(W1, b1, W2, b2, W3, b3, W4, b4);
    k_maskcalc<<<(BATCH * NODES_ALL + 255) / 256, 256>>>();
    long long nthreads = (long long)BATCH * NODES_ALL * 48;
    k_write<<<(unsigned)((nthreads + 255) / 256), 256>>>(img, out);
}